// round 5
// baseline (speedup 1.0000x reference)
#include <cuda_runtime.h>
#include <math.h>
#include <stdint.h>

#define NN 50000
#define EE 800000
#define ET 850000   // EE + NN self loops
#define NB 196      // ceil(NN/256)

// ---------------- scratch (static device allocations only) ----------------
__device__ float g_xlxr[(size_t)NN * 256];   // [0:N*128)=xl dense, [N*128:)=xr dense
__device__ float g_h1[(size_t)NN * 128];
__device__ float g_h2[(size_t)NN * 128];
__device__ float g_hlr[(size_t)NN * 32];     // conv2: [0:16)=xl2, [16:32)=xr2
__device__ int   g_deg[NN];
__device__ int   g_rowptr[NN + 1];
__device__ int   g_cursor[NN];
__device__ int   g_csr[ET];
__device__ int   g_part[256];
__device__ int   g_is64;

__device__ __forceinline__ float lrelu(float x) { return x > 0.f ? x : 0.2f * x; }
__device__ __forceinline__ float elu1 (float x) { return x > 0.f ? x : expm1f(x); }

// ---------------- cp.async helpers ----------------------------------------
__device__ __forceinline__ void cp16(uint32_t dst, const void* src, bool pred) {
    asm volatile("cp.async.ca.shared.global [%0], [%1], 16, %2;\n"
        :: "r"(dst), "l"(src), "r"(pred ? 16 : 0));
}
__device__ __forceinline__ void cp_commit() { asm volatile("cp.async.commit_group;\n"); }
__device__ __forceinline__ void cp_wait0()  { asm volatile("cp.async.wait_group 0;\n"); }

// ---------------- init deg=0 + dtype detect (block 0) ----------------------
__global__ void init_detect(const void* ei) {
    int i = blockIdx.x * blockDim.x + threadIdx.x;
    if (i < NN) g_deg[i] = 0;
    if (blockIdx.x == 0) {
        __shared__ int cnt;
        if (threadIdx.x == 0) cnt = 0;
        __syncthreads();
        const unsigned* p = (const unsigned*)ei;
        int nz = 0;
        for (int k = threadIdx.x; k < 2048; k += 256)
            if (p[2 * k + 1] != 0u) nz++;
        if (nz) atomicAdd(&cnt, nz);
        __syncthreads();
        if (threadIdx.x == 0) g_is64 = (cnt < 8) ? 1 : 0;
    }
}

__device__ __forceinline__ int edge_val(const void* ei, int idx, int is64) {
    if (is64) return (int)((const long long*)ei)[idx];
    return ((const int*)ei)[idx];
}

__global__ void degree_k(const void* ei) {
    int i = blockIdx.x * blockDim.x + threadIdx.x;
    if (i >= EE) return;
    int is64 = g_is64;
    int dst = edge_val(ei, EE + i, is64);
    atomicAdd(&g_deg[dst], 1);
}

// ---------------- parallel scan over (deg[i]+1) ----------------------------
__global__ void scan_part() {
    int t = threadIdx.x, lane = t & 31, w = t >> 5;
    int i = blockIdx.x * 256 + t;
    int v = (i < NN) ? g_deg[i] + 1 : 0;
#pragma unroll
    for (int off = 16; off >= 1; off >>= 1) v += __shfl_xor_sync(0xffffffffu, v, off);
    __shared__ int ws[8];
    if (lane == 0) ws[w] = v;
    __syncthreads();
    if (t == 0) {
        int s = 0;
#pragma unroll
        for (int k = 0; k < 8; k++) s += ws[k];
        g_part[blockIdx.x] = s;
    }
}

__global__ void scan_mid() {
    int t = threadIdx.x, lane = t & 31, w = t >> 5;
    int d = (t < NB) ? g_part[t] : 0;
    int v = d;
#pragma unroll
    for (int off = 1; off < 32; off <<= 1) {
        int u = __shfl_up_sync(0xffffffffu, v, off);
        if (lane >= off) v += u;
    }
    __shared__ int ws[8];
    if (lane == 31) ws[w] = v;
    __syncthreads();
    if (w == 0 && lane < 8) {
        int s = ws[lane];
#pragma unroll
        for (int off = 1; off < 8; off <<= 1) {
            int u = __shfl_up_sync(0xffu, s, off);
            if (lane >= off) s += u;
        }
        ws[lane] = s;
    }
    __syncthreads();
    int incl = v + (w > 0 ? ws[w - 1] : 0);
    if (t < NB) g_part[t] = incl - d;      // exclusive block offset
    if (t == 255) g_rowptr[NN] = incl;     // total (zeros beyond NB)
}

__global__ void scan_add() {
    int t = threadIdx.x, lane = t & 31, w = t >> 5;
    int i = blockIdx.x * 256 + t;
    int d = (i < NN) ? g_deg[i] + 1 : 0;
    int v = d;
#pragma unroll
    for (int off = 1; off < 32; off <<= 1) {
        int u = __shfl_up_sync(0xffffffffu, v, off);
        if (lane >= off) v += u;
    }
    __shared__ int ws[8];
    if (lane == 31) ws[w] = v;
    __syncthreads();
    if (w == 0 && lane < 8) {
        int s = ws[lane];
#pragma unroll
        for (int off = 1; off < 8; off <<= 1) {
            int u = __shfl_up_sync(0xffu, s, off);
            if (lane >= off) s += u;
        }
        ws[lane] = s;
    }
    __syncthreads();
    int excl = g_part[blockIdx.x] + v - d + (w > 0 ? ws[w - 1] : 0);
    if (i < NN) {
        g_rowptr[i] = excl;
        g_csr[excl] = i;          // self loop first
        g_cursor[i] = excl + 1;
    }
}

__global__ void scatter_k(const void* ei) {
    int i = blockIdx.x * blockDim.x + threadIdx.x;
    if (i >= EE) return;
    int is64 = g_is64;
    int s = edge_val(ei, i, is64);
    int d = edge_val(ei, EE + i, is64);
    int pos = atomicAdd(&g_cursor[d], 1);
    g_csr[pos] = s;
}

// ---------------- GEMM: C[M,128] = A[M,128] @ B[128,128] -------------------
// 64x128 tile, 128 threads, 8x8 micro-tile, cp.async double-buffered smem,
// 4 blocks/SM. grid=(782, ny). by=0 -> (B0,C0), by=1 -> (B1,C1).
// act: 0=none, 1=elu. bias may be null.
__global__ void __launch_bounds__(128, 4) gemm_tc(
    const float* __restrict__ A,
    const float* __restrict__ B0, const float* __restrict__ B1,
    float* __restrict__ C0, float* __restrict__ C1,
    int M, const float* __restrict__ bias, int act) {
    __shared__ float sA[2][64 * 16];
    __shared__ float sB[2][16 * 128];
    const int t  = threadIdx.x;
    const int tx = t & 15, ty = t >> 4;
    const int by = blockIdx.y;
    const float* Bm = by ? B1 : B0;
    float*       Cm = by ? C1 : C0;
    const int row0 = blockIdx.x * 64;

    uint32_t sA_u = (uint32_t)__cvta_generic_to_shared(&sA[0][0]);
    uint32_t sB_u = (uint32_t)__cvta_generic_to_shared(&sB[0][0]);

    float acc[8][8];
#pragma unroll
    for (int i = 0; i < 8; i++)
#pragma unroll
        for (int j = 0; j < 8; j++) acc[i][j] = 0.f;

    // per-thread fill coords
    const int ar  = (t >> 2) & 63;      // with rep offset below
    const int ac4 = (t & 3) * 4;
    const int bkk = t >> 5;             // 0..3 (+4 per rep)
    const int bc4 = (t & 31) * 4;

    // ---- fill(buf, k0) ----
#define FILL(buf, k0)                                                          \
    {                                                                          \
        _Pragma("unroll")                                                      \
        for (int rep = 0; rep < 2; rep++) {                                    \
            int r = ar + rep * 32;                                             \
            cp16(sA_u + (uint32_t)(((buf) * 64 * 16 + r * 16 + ac4) * 4),      \
                 A + (size_t)(row0 + r) * 128 + (k0) + ac4, row0 + r < M);     \
        }                                                                      \
        _Pragma("unroll")                                                      \
        for (int rep = 0; rep < 4; rep++) {                                    \
            int kk = bkk + rep * 4;                                            \
            cp16(sB_u + (uint32_t)(((buf) * 16 * 128 + kk * 128 + bc4) * 4),   \
                 Bm + (size_t)((k0) + kk) * 128 + bc4, true);                  \
        }                                                                      \
        cp_commit();                                                           \
    }

    FILL(0, 0);
    int cur = 0;
#pragma unroll
    for (int it = 0; it < 8; it++) {
        cp_wait0();
        __syncthreads();
        if (it < 7) FILL(cur ^ 1, (it + 1) * 16);
        const float* pA = &sA[cur][0];
        const float* pB = &sB[cur][0];
#pragma unroll
        for (int kg = 0; kg < 4; kg++) {
            float4 a[8];
#pragma unroll
            for (int i = 0; i < 8; i++)
                a[i] = *(const float4*)&pA[(ty * 8 + i) * 16 + kg * 4];
#pragma unroll
            for (int kk = 0; kk < 4; kk++) {
                float4 b0 = *(const float4*)&pB[(kg * 4 + kk) * 128 + tx * 8];
                float4 b1 = *(const float4*)&pB[(kg * 4 + kk) * 128 + tx * 8 + 4];
#pragma unroll
                for (int i = 0; i < 8; i++) {
                    float av = (kk == 0) ? a[i].x : (kk == 1) ? a[i].y
                             : (kk == 2) ? a[i].z : a[i].w;
                    acc[i][0] += av * b0.x; acc[i][1] += av * b0.y;
                    acc[i][2] += av * b0.z; acc[i][3] += av * b0.w;
                    acc[i][4] += av * b1.x; acc[i][5] += av * b1.y;
                    acc[i][6] += av * b1.z; acc[i][7] += av * b1.w;
                }
            }
        }
        cur ^= 1;
    }
#undef FILL

    float bv[8] = {0.f, 0.f, 0.f, 0.f, 0.f, 0.f, 0.f, 0.f};
    if (bias) {
#pragma unroll
        for (int j = 0; j < 8; j++) bv[j] = bias[tx * 8 + j];
    }
#pragma unroll
    for (int i = 0; i < 8; i++) {
        int row = row0 + ty * 8 + i;
        if (row >= M) continue;
        float v[8];
#pragma unroll
        for (int j = 0; j < 8; j++) {
            float c = acc[i][j] + bv[j];
            if (act == 1) c = elu1(c);
            v[j] = c;
        }
        *(float4*)&Cm[(size_t)row * 128 + tx * 8]     = make_float4(v[0], v[1], v[2], v[3]);
        *(float4*)&Cm[(size_t)row * 128 + tx * 8 + 4] = make_float4(v[4], v[5], v[6], v[7]);
    }
}

// ---------------- conv1 aggregation: warp per node, 8-head online softmax --
__global__ void conv1_agg(const float* __restrict__ att1, const float* __restrict__ b1) {
    int gw   = (blockIdx.x * blockDim.x + threadIdx.x) >> 5;
    int lane = threadIdx.x & 31;
    int d = gw;                                   // grid exact: 6250*8 = 50000
    const float* xlbase = g_xlxr;
    const float* xrbase = g_xlxr + (size_t)NN * 128;
    const float4 xr = *(const float4*)&xrbase[(size_t)d * 128 + lane * 4];
    const float4 av = *(const float4*)&att1[lane * 4]; // head=(lane>>2), ch=(lane&3)*4
    const float4 bb = *(const float4*)&b1[lane * 4];
    int beg = g_rowptr[d], end = g_rowptr[d + 1];

    float m = -INFINITY, s = 0.f;
    float ax = 0.f, ay = 0.f, az = 0.f, aw = 0.f;

    // 2-deep prefetch pipeline
    float4 xl0, xl1;
    xl0 = *(const float4*)&xlbase[(size_t)g_csr[beg] * 128 + lane * 4];
    if (beg + 1 < end)
        xl1 = *(const float4*)&xlbase[(size_t)g_csr[beg + 1] * 128 + lane * 4];
    for (int j = beg; j < end; j++) {
        float4 xl2;
        if (j + 2 < end)
            xl2 = *(const float4*)&xlbase[(size_t)g_csr[j + 2] * 128 + lane * 4];
        float ex = lrelu(xl0.x + xr.x);
        float ey = lrelu(xl0.y + xr.y);
        float ez = lrelu(xl0.z + xr.z);
        float ew = lrelu(xl0.w + xr.w);
        float p = ex * av.x + ey * av.y + ez * av.z + ew * av.w;
        p += __shfl_xor_sync(0xffffffffu, p, 1);
        p += __shfl_xor_sync(0xffffffffu, p, 2);   // quad = one head
        float mn = fmaxf(m, p);
        float f  = __expf(m - mn);
        float wt = __expf(p - mn);
        s  = s * f + wt;
        ax = ax * f + xl0.x * wt;
        ay = ay * f + xl0.y * wt;
        az = az * f + xl0.z * wt;
        aw = aw * f + xl0.w * wt;
        m = mn;
        xl0 = xl1; xl1 = xl2;
    }
    float inv = 1.f / s;
    float4 o;
    o.x = elu1(ax * inv + bb.x);
    o.y = elu1(ay * inv + bb.y);
    o.z = elu1(az * inv + bb.z);
    o.w = elu1(aw * inv + bb.w);
    *(float4*)&g_h1[(size_t)d * 128 + lane * 4] = o;
}

// ---------------- conv2 transforms: [N,32] = h @ [Wl2|Wr2] -----------------
__global__ void conv2_transform(const float* __restrict__ h,
                                const float* __restrict__ Wl2,
                                const float* __restrict__ Wr2) {
    __shared__ float sw[128 * 32];
    __shared__ float sh[8][128];
    int t = threadIdx.x;
    for (int i = t; i < 128 * 16; i += 256) {
        int k = i >> 4, c = i & 15;
        sw[k * 32 + c]      = Wl2[i];
        sw[k * 32 + 16 + c] = Wr2[i];
    }
    int row0 = blockIdx.x * 8;
    for (int i = t; i < 8 * 128; i += 256) {
        int r = i >> 7;
        sh[r][i & 127] = h[(size_t)(row0 + r) * 128 + (i & 127)];
    }
    __syncthreads();
    int warp = t >> 5, lane = t & 31;
    int row = row0 + warp;                        // exact grid: 6250*8 = 50000
    float acc = 0.f;
#pragma unroll
    for (int k = 0; k < 128; k++) acc += sh[warp][k] * sw[k * 32 + lane];
    g_hlr[(size_t)row * 32 + lane] = acc;
}

// ---------------- conv2 aggregation + log_softmax: half-warp per node ------
__global__ void conv2_agg(const float* __restrict__ att2, const float* __restrict__ b2,
                          float* __restrict__ out) {
    int tid = blockIdx.x * blockDim.x + threadIdx.x;
    int d = tid >> 4;                             // exact grid: 3125*16 = 50000
    int l = tid & 15;
    unsigned hm = 0xFFFFu << (((threadIdx.x & 31) >> 4) * 16);  // own half-warp

    float xr = g_hlr[(size_t)d * 32 + 16 + l];
    float a  = att2[l];
    int beg = g_rowptr[d], end = g_rowptr[d + 1];

    float m = -INFINITY, s = 0.f, acc = 0.f;
    int src = g_csr[beg];
    float xl = g_hlr[(size_t)src * 32 + l];
    for (int j = beg; j < end; j++) {
        float xln = 0.f;
        if (j + 1 < end) {
            int nsrc = g_csr[j + 1];
            xln = g_hlr[(size_t)nsrc * 32 + l];
        }
        float p = lrelu(xl + xr) * a;
        p += __shfl_xor_sync(hm, p, 1);
        p += __shfl_xor_sync(hm, p, 2);
        p += __shfl_xor_sync(hm, p, 4);
        p += __shfl_xor_sync(hm, p, 8);
        float mn = fmaxf(m, p);
        float f  = __expf(m - mn);
        float w  = __expf(p - mn);
        s   = s * f + w;
        acc = acc * f + xl * w;
        m = mn;
        xl = xln;
    }
    float v = acc / s + b2[l];
    // log_softmax over the 16 channels (the 16 lanes of this half-warp)
    float mm = v;
#pragma unroll
    for (int k = 8; k >= 1; k >>= 1) mm = fmaxf(mm, __shfl_xor_sync(hm, mm, k));
    float pe = expf(v - mm);
    float ss = pe;
#pragma unroll
    for (int k = 8; k >= 1; k >>= 1) ss += __shfl_xor_sync(hm, ss, k);
    out[(size_t)d * 16 + l] = v - mm - logf(ss);
}

// ---------------- side stream for CSR build (created at static init) -------
static cudaStream_t s_csr = 0;
static cudaEvent_t  ev_fork = 0, ev_join = 0;
namespace {
struct StreamInit {
    StreamInit() {
        cudaStreamCreateWithFlags(&s_csr, cudaStreamNonBlocking);
        cudaEventCreateWithFlags(&ev_fork, cudaEventDisableTiming);
        cudaEventCreateWithFlags(&ev_join, cudaEventDisableTiming);
    }
} s_init;
}

// ---------------- launch ----------------
extern "C" void kernel_launch(void* const* d_in, const int* in_sizes, int n_in,
                              void* d_out, int out_size) {
    const float* x    = (const float*)d_in[0];
    const void*  ei   = d_in[1];
    const float* Wl1  = (const float*)d_in[2];
    const float* Wr1  = (const float*)d_in[3];
    const float* att1 = (const float*)d_in[4];
    const float* b1   = (const float*)d_in[5];
    const float* Wk   = (const float*)d_in[6];
    const float* bk   = (const float*)d_in[7];
    const float* Wl2  = (const float*)d_in[8];
    const float* Wr2  = (const float*)d_in[9];
    const float* att2 = (const float*)d_in[10];
    const float* b2   = (const float*)d_in[11];
    float* out = (float*)d_out;

    float *xlxr, *h1, *h2;
    cudaGetSymbolAddress((void**)&xlxr, g_xlxr);
    cudaGetSymbolAddress((void**)&h1, g_h1);
    cudaGetSymbolAddress((void**)&h2, g_h2);
    float* xl = xlxr;
    float* xr = xlxr + (size_t)NN * 128;

    const int GX = (NN + 63) / 64;   // 782
    dim3 g2(GX, 2);
    dim3 g1(GX, 1);

    // deg=0 + dtype detect (needed by both branches)
    init_detect<<<NB, 256>>>(ei);

    // ---- fork: CSR build on side stream, conv1 GEMM on main stream ----
    cudaEventRecord(ev_fork, 0);
    cudaStreamWaitEvent(s_csr, ev_fork, 0);

    degree_k <<<(EE + 255) / 256, 256, 0, s_csr>>>(ei);
    scan_part<<<NB, 256, 0, s_csr>>>();
    scan_mid <<<1, 256, 0, s_csr>>>();
    scan_add <<<NB, 256, 0, s_csr>>>();
    scatter_k<<<(EE + 255) / 256, 256, 0, s_csr>>>(ei);
    cudaEventRecord(ev_join, s_csr);

    // conv1 xl+xr transforms (main stream, overlaps CSR build)
    gemm_tc<<<g2, 128>>>(x, Wl1, Wr1, xl, xr, NN, nullptr, 0);

    // ---- join ----
    cudaStreamWaitEvent(0, ev_join, 0);

    // conv1 aggregation (+elu) -> g_h1
    conv1_agg<<<NN / 8, 256>>>(att1, b1);

    // knowledge layers (elu fused)
    gemm_tc<<<g1, 128>>>(h1, Wk,                 nullptr, h2, nullptr, NN, bk,       1);
    gemm_tc<<<g1, 128>>>(h2, Wk + 128 * 128,     nullptr, h1, nullptr, NN, bk + 128, 1);
    gemm_tc<<<g1, 128>>>(h1, Wk + 2 * 128 * 128, nullptr, h2, nullptr, NN, bk + 256, 1);

    // conv2 transforms -> g_hlr
    conv2_transform<<<NN / 8, 256>>>(h2, Wl2, Wr2);

    // conv2 aggregation + log_softmax -> out
    conv2_agg<<<NN / 16, 256>>>(att2, b2, out);
}

// round 6
// speedup vs baseline: 1.0774x; 1.0774x over previous
#include <cuda_runtime.h>
#include <math.h>
#include <stdint.h>

#define NN 50000
#define EE 800000
#define ET 850000   // EE + NN self loops
#define NB 196      // ceil(NN/256)

// ---------------- scratch (static device allocations only) ----------------
__device__ float g_xlxr[(size_t)NN * 256];   // [0:N*128)=xl dense, [N*128:)=xr dense
__device__ float g_h1[(size_t)NN * 128];
__device__ float g_h2[(size_t)NN * 128];
__device__ float g_hlr[(size_t)NN * 32];     // conv2: [0:16)=xl2, [16:32)=xr2
__device__ int   g_deg[NN];
__device__ int   g_rowptr[NN + 1];
__device__ int   g_cursor[NN];
__device__ int   g_csr[ET];
__device__ int   g_part[256];
__device__ int   g_is64;

__device__ __forceinline__ float lrelu(float x) { return x > 0.f ? x : 0.2f * x; }
__device__ __forceinline__ float elu1 (float x) { return x > 0.f ? x : expm1f(x); }

// ---------------- init deg=0 + dtype detect (block 0) ----------------------
__global__ void init_detect(const void* ei) {
    int i = blockIdx.x * blockDim.x + threadIdx.x;
    if (i < NN) g_deg[i] = 0;
    if (blockIdx.x == 0) {
        __shared__ int cnt;
        if (threadIdx.x == 0) cnt = 0;
        __syncthreads();
        const unsigned* p = (const unsigned*)ei;
        int nz = 0;
        for (int k = threadIdx.x; k < 2048; k += 256)
            if (p[2 * k + 1] != 0u) nz++;
        if (nz) atomicAdd(&cnt, nz);
        __syncthreads();
        if (threadIdx.x == 0) g_is64 = (cnt < 8) ? 1 : 0;
    }
}

__device__ __forceinline__ int edge_val(const void* ei, int idx, int is64) {
    if (is64) return (int)((const long long*)ei)[idx];
    return ((const int*)ei)[idx];
}

__global__ void degree_k(const void* ei) {
    int i = blockIdx.x * blockDim.x + threadIdx.x;
    if (i >= EE) return;
    int is64 = g_is64;
    int dst = edge_val(ei, EE + i, is64);
    atomicAdd(&g_deg[dst], 1);
}

// ---------------- parallel scan over (deg[i]+1) ----------------------------
__global__ void scan_part() {
    int t = threadIdx.x, lane = t & 31, w = t >> 5;
    int i = blockIdx.x * 256 + t;
    int v = (i < NN) ? g_deg[i] + 1 : 0;
#pragma unroll
    for (int off = 16; off >= 1; off >>= 1) v += __shfl_xor_sync(0xffffffffu, v, off);
    __shared__ int ws[8];
    if (lane == 0) ws[w] = v;
    __syncthreads();
    if (t == 0) {
        int s = 0;
#pragma unroll
        for (int k = 0; k < 8; k++) s += ws[k];
        g_part[blockIdx.x] = s;
    }
}

__global__ void scan_mid() {
    int t = threadIdx.x, lane = t & 31, w = t >> 5;
    int d = (t < NB) ? g_part[t] : 0;
    int v = d;
#pragma unroll
    for (int off = 1; off < 32; off <<= 1) {
        int u = __shfl_up_sync(0xffffffffu, v, off);
        if (lane >= off) v += u;
    }
    __shared__ int ws[8];
    if (lane == 31) ws[w] = v;
    __syncthreads();
    if (w == 0 && lane < 8) {
        int s = ws[lane];
#pragma unroll
        for (int off = 1; off < 8; off <<= 1) {
            int u = __shfl_up_sync(0xffu, s, off);
            if (lane >= off) s += u;
        }
        ws[lane] = s;
    }
    __syncthreads();
    int incl = v + (w > 0 ? ws[w - 1] : 0);
    if (t < NB) g_part[t] = incl - d;      // exclusive block offset
    if (t == 255) g_rowptr[NN] = incl;     // total (zeros beyond NB)
}

__global__ void scan_add() {
    int t = threadIdx.x, lane = t & 31, w = t >> 5;
    int i = blockIdx.x * 256 + t;
    int d = (i < NN) ? g_deg[i] + 1 : 0;
    int v = d;
#pragma unroll
    for (int off = 1; off < 32; off <<= 1) {
        int u = __shfl_up_sync(0xffffffffu, v, off);
        if (lane >= off) v += u;
    }
    __shared__ int ws[8];
    if (lane == 31) ws[w] = v;
    __syncthreads();
    if (w == 0 && lane < 8) {
        int s = ws[lane];
#pragma unroll
        for (int off = 1; off < 8; off <<= 1) {
            int u = __shfl_up_sync(0xffu, s, off);
            if (lane >= off) s += u;
        }
        ws[lane] = s;
    }
    __syncthreads();
    int excl = g_part[blockIdx.x] + v - d + (w > 0 ? ws[w - 1] : 0);
    if (i < NN) {
        g_rowptr[i] = excl;
        g_csr[excl] = i;          // self loop first
        g_cursor[i] = excl + 1;
    }
}

__global__ void scatter_k(const void* ei) {
    int i = blockIdx.x * blockDim.x + threadIdx.x;
    if (i >= EE) return;
    int is64 = g_is64;
    int s = edge_val(ei, i, is64);
    int d = edge_val(ei, EE + i, is64);
    int pos = atomicAdd(&g_cursor[d], 1);
    g_csr[pos] = s;
}

// ---------------- GEMM: C[M,128] = A[M,128] @ B[128,128] -------------------
// 128x64 tile, 256 threads, 8x4 micro-tile, K=128, double-buffered smem,
// forced 4 blocks/SM (Round-4 proven config). grid=(ceil(M/128), ny).
// by<2 -> (B0,C0), else (B1,C1), col0=(by&1)*64.
__global__ void __launch_bounds__(256, 4) gemm128t(
    const float* __restrict__ A,
    const float* __restrict__ B0, const float* __restrict__ B1,
    float* __restrict__ C0, float* __restrict__ C1, int M,
    const float* __restrict__ bias, int act) {
    __shared__ float sA[2][16][132];
    __shared__ float sB[2][16][64];
    int t  = threadIdx.x;
    int tx = t & 15, ty = t >> 4;
    int by = blockIdx.y;
    const float* B = (by < 2) ? B0 : B1;
    float*       C = (by < 2) ? C0 : C1;
    int row0 = blockIdx.x * 128;
    int col0 = (by & 1) * 64;

    int ar  = t >> 2;            // 0..63
    int akc = (t & 3) * 4;       // 0,4,8,12
    int bkk = t >> 4;            // 0..15
    int bnc = (t & 15) * 4;      // 0..60

    float acc[8][4];
#pragma unroll
    for (int i = 0; i < 8; i++)
#pragma unroll
        for (int j = 0; j < 4; j++) acc[i][j] = 0.f;

    float4 pa0, pa1, pb;
    int gr0 = row0 + ar, gr1 = row0 + ar + 64;

    // prologue: tile 0
    pa0 = (gr0 < M) ? *(const float4*)&A[(size_t)gr0 * 128 + akc] : make_float4(0, 0, 0, 0);
    pa1 = (gr1 < M) ? *(const float4*)&A[(size_t)gr1 * 128 + akc] : make_float4(0, 0, 0, 0);
    pb  = *(const float4*)&B[(size_t)bkk * 128 + col0 + bnc];
    {
        sA[0][akc + 0][ar] = pa0.x; sA[0][akc + 1][ar] = pa0.y;
        sA[0][akc + 2][ar] = pa0.z; sA[0][akc + 3][ar] = pa0.w;
        sA[0][akc + 0][ar + 64] = pa1.x; sA[0][akc + 1][ar + 64] = pa1.y;
        sA[0][akc + 2][ar + 64] = pa1.z; sA[0][akc + 3][ar + 64] = pa1.w;
        *(float4*)&sB[0][bkk][bnc] = pb;
    }
    __syncthreads();

    int cur = 0;
#pragma unroll
    for (int it = 0; it < 8; it++) {
        if (it < 7) {
            int k0 = (it + 1) * 16;
            pa0 = (gr0 < M) ? *(const float4*)&A[(size_t)gr0 * 128 + k0 + akc] : make_float4(0, 0, 0, 0);
            pa1 = (gr1 < M) ? *(const float4*)&A[(size_t)gr1 * 128 + k0 + akc] : make_float4(0, 0, 0, 0);
            pb  = *(const float4*)&B[(size_t)(k0 + bkk) * 128 + col0 + bnc];
        }
#pragma unroll
        for (int kk = 0; kk < 16; kk++) {
            float4 a0 = *(float4*)&sA[cur][kk][ty * 8];
            float4 a1 = *(float4*)&sA[cur][kk][ty * 8 + 4];
            float4 b  = *(float4*)&sB[cur][kk][tx * 4];
            acc[0][0] += a0.x * b.x; acc[0][1] += a0.x * b.y; acc[0][2] += a0.x * b.z; acc[0][3] += a0.x * b.w;
            acc[1][0] += a0.y * b.x; acc[1][1] += a0.y * b.y; acc[1][2] += a0.y * b.z; acc[1][3] += a0.y * b.w;
            acc[2][0] += a0.z * b.x; acc[2][1] += a0.z * b.y; acc[2][2] += a0.z * b.z; acc[2][3] += a0.z * b.w;
            acc[3][0] += a0.w * b.x; acc[3][1] += a0.w * b.y; acc[3][2] += a0.w * b.z; acc[3][3] += a0.w * b.w;
            acc[4][0] += a1.x * b.x; acc[4][1] += a1.x * b.y; acc[4][2] += a1.x * b.z; acc[4][3] += a1.x * b.w;
            acc[5][0] += a1.y * b.x; acc[5][1] += a1.y * b.y; acc[5][2] += a1.y * b.z; acc[5][3] += a1.y * b.w;
            acc[6][0] += a1.z * b.x; acc[6][1] += a1.z * b.y; acc[6][2] += a1.z * b.z; acc[6][3] += a1.z * b.w;
            acc[7][0] += a1.w * b.x; acc[7][1] += a1.w * b.y; acc[7][2] += a1.w * b.z; acc[7][3] += a1.w * b.w;
        }
        if (it < 7) {
            int nb = cur ^ 1;
            sA[nb][akc + 0][ar] = pa0.x; sA[nb][akc + 1][ar] = pa0.y;
            sA[nb][akc + 2][ar] = pa0.z; sA[nb][akc + 3][ar] = pa0.w;
            sA[nb][akc + 0][ar + 64] = pa1.x; sA[nb][akc + 1][ar + 64] = pa1.y;
            sA[nb][akc + 2][ar + 64] = pa1.z; sA[nb][akc + 3][ar + 64] = pa1.w;
            *(float4*)&sB[nb][bkk][bnc] = pb;
            __syncthreads();
            cur = nb;
        }
    }

    float bv[4] = {0.f, 0.f, 0.f, 0.f};
    if (bias) {
#pragma unroll
        for (int j = 0; j < 4; j++) bv[j] = bias[col0 + tx * 4 + j];
    }
#pragma unroll
    for (int i = 0; i < 8; i++) {
        int row = row0 + ty * 8 + i;
        if (row >= M) continue;
        float v[4];
#pragma unroll
        for (int j = 0; j < 4; j++) {
            float c = acc[i][j] + bv[j];
            if (act == 1) c = elu1(c);
            v[j] = c;
        }
        *(float4*)&C[(size_t)row * 128 + col0 + tx * 4] =
            make_float4(v[0], v[1], v[2], v[3]);
    }
}

// ---------------- conv1 aggregation: warp per node, 8-head online softmax --
__global__ void conv1_agg(const float* __restrict__ att1, const float* __restrict__ b1) {
    int gw   = (blockIdx.x * blockDim.x + threadIdx.x) >> 5;
    int lane = threadIdx.x & 31;
    int d = gw;                                   // grid exact: 6250*8 = 50000
    const float* xlbase = g_xlxr;
    const float* xrbase = g_xlxr + (size_t)NN * 128;
    const float4 xr = *(const float4*)&xrbase[(size_t)d * 128 + lane * 4];
    const float4 av = *(const float4*)&att1[lane * 4]; // head=(lane>>2), ch=(lane&3)*4
    const float4 bb = *(const float4*)&b1[lane * 4];
    int beg = g_rowptr[d], end = g_rowptr[d + 1];

    float m = -INFINITY, s = 0.f;
    float ax = 0.f, ay = 0.f, az = 0.f, aw = 0.f;

    // 2-deep prefetch pipeline
    float4 xl0, xl1;
    xl0 = *(const float4*)&xlbase[(size_t)g_csr[beg] * 128 + lane * 4];
    if (beg + 1 < end)
        xl1 = *(const float4*)&xlbase[(size_t)g_csr[beg + 1] * 128 + lane * 4];
    for (int j = beg; j < end; j++) {
        float4 xl2;
        if (j + 2 < end)
            xl2 = *(const float4*)&xlbase[(size_t)g_csr[j + 2] * 128 + lane * 4];
        float ex = lrelu(xl0.x + xr.x);
        float ey = lrelu(xl0.y + xr.y);
        float ez = lrelu(xl0.z + xr.z);
        float ew = lrelu(xl0.w + xr.w);
        float p = ex * av.x + ey * av.y + ez * av.z + ew * av.w;
        p += __shfl_xor_sync(0xffffffffu, p, 1);
        p += __shfl_xor_sync(0xffffffffu, p, 2);   // quad = one head
        float mn = fmaxf(m, p);
        float f  = __expf(m - mn);
        float wt = __expf(p - mn);
        s  = s * f + wt;
        ax = ax * f + xl0.x * wt;
        ay = ay * f + xl0.y * wt;
        az = az * f + xl0.z * wt;
        aw = aw * f + xl0.w * wt;
        m = mn;
        xl0 = xl1; xl1 = xl2;
    }
    float inv = 1.f / s;
    float4 o;
    o.x = elu1(ax * inv + bb.x);
    o.y = elu1(ay * inv + bb.y);
    o.z = elu1(az * inv + bb.z);
    o.w = elu1(aw * inv + bb.w);
    *(float4*)&g_h1[(size_t)d * 128 + lane * 4] = o;
}

// ---------------- conv2 transforms: [N,32] = h @ [Wl2|Wr2] -----------------
__global__ void conv2_transform(const float* __restrict__ h,
                                const float* __restrict__ Wl2,
                                const float* __restrict__ Wr2) {
    __shared__ float sw[128 * 32];
    __shared__ float sh[8][128];
    int t = threadIdx.x;
    for (int i = t; i < 128 * 16; i += 256) {
        int k = i >> 4, c = i & 15;
        sw[k * 32 + c]      = Wl2[i];
        sw[k * 32 + 16 + c] = Wr2[i];
    }
    int row0 = blockIdx.x * 8;
    for (int i = t; i < 8 * 128; i += 256) {
        int r = i >> 7;
        sh[r][i & 127] = h[(size_t)(row0 + r) * 128 + (i & 127)];
    }
    __syncthreads();
    int warp = t >> 5, lane = t & 31;
    int row = row0 + warp;                        // exact grid: 6250*8 = 50000
    float acc = 0.f;
#pragma unroll
    for (int k = 0; k < 128; k++) acc += sh[warp][k] * sw[k * 32 + lane];
    g_hlr[(size_t)row * 32 + lane] = acc;
}

// ---------------- conv2 aggregation + log_softmax: half-warp per node ------
__global__ void conv2_agg(const float* __restrict__ att2, const float* __restrict__ b2,
                          float* __restrict__ out) {
    int tid = blockIdx.x * blockDim.x + threadIdx.x;
    int d = tid >> 4;                             // exact grid: 3125*16 = 50000
    int l = tid & 15;
    unsigned hm = 0xFFFFu << (((threadIdx.x & 31) >> 4) * 16);  // own half-warp

    float xr = g_hlr[(size_t)d * 32 + 16 + l];
    float a  = att2[l];
    int beg = g_rowptr[d], end = g_rowptr[d + 1];

    float m = -INFINITY, s = 0.f, acc = 0.f;
    int src = g_csr[beg];
    float xl = g_hlr[(size_t)src * 32 + l];
    for (int j = beg; j < end; j++) {
        float xln = 0.f;
        if (j + 1 < end) {
            int nsrc = g_csr[j + 1];
            xln = g_hlr[(size_t)nsrc * 32 + l];
        }
        float p = lrelu(xl + xr) * a;
        p += __shfl_xor_sync(hm, p, 1);
        p += __shfl_xor_sync(hm, p, 2);
        p += __shfl_xor_sync(hm, p, 4);
        p += __shfl_xor_sync(hm, p, 8);
        float mn = fmaxf(m, p);
        float f  = __expf(m - mn);
        float w  = __expf(p - mn);
        s   = s * f + w;
        acc = acc * f + xl * w;
        m = mn;
        xl = xln;
    }
    float v = acc / s + b2[l];
    // log_softmax over the 16 channels (the 16 lanes of this half-warp)
    float mm = v;
#pragma unroll
    for (int k = 8; k >= 1; k >>= 1) mm = fmaxf(mm, __shfl_xor_sync(hm, mm, k));
    float pe = expf(v - mm);
    float ss = pe;
#pragma unroll
    for (int k = 8; k >= 1; k >>= 1) ss += __shfl_xor_sync(hm, ss, k);
    out[(size_t)d * 16 + l] = v - mm - logf(ss);
}

// ---------------- side stream for CSR build (created at static init) -------
static cudaStream_t s_csr = 0;
static cudaEvent_t  ev_fork = 0, ev_join = 0;
namespace {
struct StreamInit {
    StreamInit() {
        cudaStreamCreateWithFlags(&s_csr, cudaStreamNonBlocking);
        cudaEventCreateWithFlags(&ev_fork, cudaEventDisableTiming);
        cudaEventCreateWithFlags(&ev_join, cudaEventDisableTiming);
    }
} s_init;
}

// ---------------- launch ----------------
extern "C" void kernel_launch(void* const* d_in, const int* in_sizes, int n_in,
                              void* d_out, int out_size) {
    const float* x    = (const float*)d_in[0];
    const void*  ei   = d_in[1];
    const float* Wl1  = (const float*)d_in[2];
    const float* Wr1  = (const float*)d_in[3];
    const float* att1 = (const float*)d_in[4];
    const float* b1   = (const float*)d_in[5];
    const float* Wk   = (const float*)d_in[6];
    const float* bk   = (const float*)d_in[7];
    const float* Wl2  = (const float*)d_in[8];
    const float* Wr2  = (const float*)d_in[9];
    const float* att2 = (const float*)d_in[10];
    const float* b2   = (const float*)d_in[11];
    float* out = (float*)d_out;

    float *xlxr, *h1, *h2;
    cudaGetSymbolAddress((void**)&xlxr, g_xlxr);
    cudaGetSymbolAddress((void**)&h1, g_h1);
    cudaGetSymbolAddress((void**)&h2, g_h2);
    float* xl = xlxr;
    float* xr = xlxr + (size_t)NN * 128;

    dim3 g4((NN + 127) / 128, 4);   // conv1 xl+xr in one launch
    dim3 g2((NN + 127) / 128, 2);   // knowledge layers

    // deg=0 + dtype detect (needed by both branches)
    init_detect<<<NB, 256>>>(ei);

    // ---- fork: CSR build on side stream, conv1 GEMM on main stream ----
    cudaEventRecord(ev_fork, 0);
    cudaStreamWaitEvent(s_csr, ev_fork, 0);

    degree_k <<<(EE + 255) / 256, 256, 0, s_csr>>>(ei);
    scan_part<<<NB, 256, 0, s_csr>>>();
    scan_mid <<<1, 256, 0, s_csr>>>();
    scan_add <<<NB, 256, 0, s_csr>>>();
    scatter_k<<<(EE + 255) / 256, 256, 0, s_csr>>>(ei);
    cudaEventRecord(ev_join, s_csr);

    // conv1 xl+xr transforms (main stream, overlaps CSR build)
    gemm128t<<<g4, 256>>>(x, Wl1, Wr1, xl, xr, NN, nullptr, 0);

    // ---- join ----
    cudaStreamWaitEvent(0, ev_join, 0);

    // conv1 aggregation (+elu) -> g_h1
    conv1_agg<<<NN / 8, 256>>>(att1, b1);

    // knowledge layers (elu fused)
    gemm128t<<<g2, 256>>>(h1, Wk,                 nullptr, h2, nullptr, NN, bk,       1);
    gemm128t<<<g2, 256>>>(h2, Wk + 128 * 128,     nullptr, h1, nullptr, NN, bk + 128, 1);
    gemm128t<<<g2, 256>>>(h1, Wk + 2 * 128 * 128, nullptr, h2, nullptr, NN, bk + 256, 1);

    // conv2 transforms -> g_hlr
    conv2_transform<<<NN / 8, 256>>>(h2, Wl2, Wr2);

    // conv2 aggregation + log_softmax -> out
    conv2_agg<<<NN / 16, 256>>>(att2, b2, out);
}

// round 8
// speedup vs baseline: 1.1684x; 1.0845x over previous
#include <cuda_runtime.h>
#include <cuda_bf16.h>
#include <math.h>
#include <stdint.h>

#define NN 50000
#define EE 800000
#define ET 850000   // EE + NN self loops
#define NB 196      // ceil(NN/256)
#define GX64 782    // ceil(NN/64)
#define WPAD 72     // padded smem row: 72 bf16 = 144B (conflict-free ldmatrix)
#define GPAD 136    // padded global image row: 136 bf16 = 272B

// ---------------- scratch (static device allocations only) ----------------
__device__ float g_xlxr[(size_t)NN * 256];   // [0:N*128)=xl dense, [N*128:)=xr dense
__device__ float g_h1[(size_t)NN * 128];
__device__ float g_h2[(size_t)NN * 128];
__device__ float g_hlr[(size_t)NN * 32];
__device__ int   g_deg[NN];
__device__ int   g_rowptr[NN + 1];
__device__ int   g_cursor[NN];
__device__ int   g_csr[ET];
__device__ int   g_part[256];
__device__ int   g_is64;
// weight images: [matrix 0..4][hi/lo] as [k][n] rows padded to 272B
__device__ __align__(16) __nv_bfloat16 g_wimg[5][2][128 * GPAD];

__device__ __forceinline__ float lrelu(float x) { return x > 0.f ? x : 0.2f * x; }
__device__ __forceinline__ float elu1 (float x) { return x > 0.f ? x : expm1f(x); }

__device__ __forceinline__ uint32_t smem_u32(const void* p) {
    uint32_t a;
    asm("{ .reg .u64 t; cvta.to.shared.u64 t, %1; cvt.u32.u64 %0, t; }"
        : "=r"(a) : "l"(p));
    return a;
}
__device__ __forceinline__ uint32_t pk2(__nv_bfloat16 a, __nv_bfloat16 b) {
    return (uint32_t)__bfloat16_as_ushort(a) | ((uint32_t)__bfloat16_as_ushort(b) << 16);
}
// split float2 into bf16x2 hi + bf16x2 lo (residual)
__device__ __forceinline__ void split2(float2 f, uint32_t& h, uint32_t& l) {
    __nv_bfloat16 hx = __float2bfloat16_rn(f.x);
    __nv_bfloat16 hy = __float2bfloat16_rn(f.y);
    float rx = f.x - __bfloat162float(hx);
    float ry = f.y - __bfloat162float(hy);
    h = pk2(hx, hy);
    l = pk2(__float2bfloat16_rn(rx), __float2bfloat16_rn(ry));
}

__device__ __forceinline__ void ldsm_x4t(uint32_t& r0, uint32_t& r1,
                                         uint32_t& r2, uint32_t& r3, uint32_t addr) {
    asm volatile("ldmatrix.sync.aligned.m8n8.x4.trans.shared.b16 {%0,%1,%2,%3}, [%4];"
        : "=r"(r0), "=r"(r1), "=r"(r2), "=r"(r3) : "r"(addr));
}
__device__ __forceinline__ void mma16816(float* d, const uint32_t* a,
                                         uint32_t b0, uint32_t b1) {
    asm volatile(
        "mma.sync.aligned.m16n8k16.row.col.f32.bf16.bf16.f32 "
        "{%0,%1,%2,%3}, {%4,%5,%6,%7}, {%8,%9}, {%0,%1,%2,%3};"
        : "+f"(d[0]), "+f"(d[1]), "+f"(d[2]), "+f"(d[3])
        : "r"(a[0]), "r"(a[1]), "r"(a[2]), "r"(a[3]), "r"(b0), "r"(b1));
}

// ---------------- weight split kernel: W[k][n] -> hi/lo images --------------
__global__ void wconv(const float* __restrict__ w0, const float* __restrict__ w1,
                      const float* __restrict__ w2, const float* __restrict__ w3,
                      const float* __restrict__ w4) {
    int b = blockIdx.x;
    const float* W = (b == 0) ? w0 : (b == 1) ? w1 : (b == 2) ? w2 : (b == 3) ? w3 : w4;
    __nv_bfloat16* hi = g_wimg[b][0];
    __nv_bfloat16* lo = g_wimg[b][1];
    int n = threadIdx.x;   // 0..127
    for (int k = 0; k < 128; k++) {
        float v = W[(size_t)k * 128 + n];
        __nv_bfloat16 h = __float2bfloat16_rn(v);
        __nv_bfloat16 l = __float2bfloat16_rn(v - __bfloat162float(h));
        hi[k * GPAD + n] = h;
        lo[k * GPAD + n] = l;
    }
}

// ---------------- tensor-core GEMM: C[NN,128] = A[NN,128] @ W --------------
// bf16 hi/lo split, 3 mma passes, fp32 accum. grid=(782, 2*nmat), 128 thr.
// by: mat = by>>1 selects (img,C); half = by&1 selects 64-col slice.
__global__ void __launch_bounds__(128) mma_gemm(
    const float* __restrict__ A, int i0, int i1,
    float* __restrict__ C0, float* __restrict__ C1,
    const float* __restrict__ bias, int act) {
    __shared__ __align__(16) __nv_bfloat16 sB[2][128 * WPAD];
    const int t = threadIdx.x, lane = t & 31, wid = t >> 5;
    const int by = blockIdx.y;
    const int mat = by >> 1, half = by & 1;
    const int img = mat ? i1 : i0;
    float* C = mat ? C1 : C0;
    const int m0 = blockIdx.x * 64 + wid * 16;

    // stage B hi/lo 64-col slice into smem (16B chunks)
    {
        const uint4* srcH = (const uint4*)&g_wimg[img][0][0];
        const uint4* srcL = (const uint4*)&g_wimg[img][1][0];
        uint4* dstH = (uint4*)&sB[0][0];
        uint4* dstL = (uint4*)&sB[1][0];
        for (int idx = t; idx < 1024; idx += 128) {
            int r = idx >> 3, c = idx & 7;          // row k, 16B chunk
            dstH[r * 9 + c] = srcH[r * 17 + half * 8 + c];
            dstL[r * 9 + c] = srcL[r * 17 + half * 8 + c];
        }
    }
    __syncthreads();

    const int g  = lane >> 2;        // fragment row group 0..7
    const int cp = (lane & 3) * 2;   // fragment col pair
    const float* Ar0 = A + (size_t)(m0 + g) * 128;
    const float* Ar8 = A + (size_t)(m0 + g + 8) * 128;
    const bool v0 = (m0 + g) < NN;
    const bool v8 = (m0 + g + 8) < NN;

    // ldmatrix per-thread address pieces
    const int bi   = lane >> 3;
    const int brow = (lane & 7) + (bi & 1) * 8;
    const int bcol = (bi >> 1) * 8;
    const uint32_t sbH = smem_u32(&sB[0][0]);
    const uint32_t sbL = smem_u32(&sB[1][0]);

    float acc[8][4];
#pragma unroll
    for (int i = 0; i < 8; i++)
#pragma unroll
        for (int j = 0; j < 4; j++) acc[i][j] = 0.f;

    for (int ks = 0; ks < 8; ks++) {
        const int k0 = ks * 16;
        // A fragment straight from global, split hi/lo
        float2 f0 = v0 ? *(const float2*)(Ar0 + k0 + cp)     : make_float2(0.f, 0.f);
        float2 f1 = v8 ? *(const float2*)(Ar8 + k0 + cp)     : make_float2(0.f, 0.f);
        float2 f2 = v0 ? *(const float2*)(Ar0 + k0 + cp + 8) : make_float2(0.f, 0.f);
        float2 f3 = v8 ? *(const float2*)(Ar8 + k0 + cp + 8) : make_float2(0.f, 0.f);
        uint32_t ah[4], al[4];
        split2(f0, ah[0], al[0]);
        split2(f1, ah[1], al[1]);
        split2(f2, ah[2], al[2]);
        split2(f3, ah[3], al[3]);

        const uint32_t rowoff = (uint32_t)((k0 + brow) * WPAD + bcol) * 2;
#pragma unroll
        for (int ng = 0; ng < 4; ng++) {
            uint32_t bh0, bh1, bh2, bh3, bl0, bl1, bl2, bl3;
            ldsm_x4t(bh0, bh1, bh2, bh3, sbH + rowoff + ng * 32);
            ldsm_x4t(bl0, bl1, bl2, bl3, sbL + rowoff + ng * 32);
            mma16816(acc[2 * ng],     ah, bh0, bh1);
            mma16816(acc[2 * ng + 1], ah, bh2, bh3);
            mma16816(acc[2 * ng],     ah, bl0, bl1);
            mma16816(acc[2 * ng + 1], ah, bl2, bl3);
            mma16816(acc[2 * ng],     al, bh0, bh1);
            mma16816(acc[2 * ng + 1], al, bh2, bh3);
        }
    }

    // epilogue
    const int r0w = m0 + g, r8w = m0 + g + 8;
#pragma unroll
    for (int nt = 0; nt < 8; nt++) {
        int gc = half * 64 + nt * 8 + cp;
        float v00 = acc[nt][0], v01 = acc[nt][1];
        float v10 = acc[nt][2], v11 = acc[nt][3];
        if (bias) {
            float b0v = bias[gc], b1v = bias[gc + 1];
            v00 += b0v; v01 += b1v; v10 += b0v; v11 += b1v;
        }
        if (act == 1) { v00 = elu1(v00); v01 = elu1(v01); v10 = elu1(v10); v11 = elu1(v11); }
        if (v0) *(float2*)&C[(size_t)r0w * 128 + gc] = make_float2(v00, v01);
        if (v8) *(float2*)&C[(size_t)r8w * 128 + gc] = make_float2(v10, v11);
    }
}

// ---------------- init deg=0 + dtype detect (block 0) ----------------------
__global__ void init_detect(const void* ei) {
    int i = blockIdx.x * blockDim.x + threadIdx.x;
    if (i < NN) g_deg[i] = 0;
    if (blockIdx.x == 0) {
        __shared__ int cnt;
        if (threadIdx.x == 0) cnt = 0;
        __syncthreads();
        const unsigned* p = (const unsigned*)ei;
        int nz = 0;
        for (int k = threadIdx.x; k < 2048; k += 256)
            if (p[2 * k + 1] != 0u) nz++;
        if (nz) atomicAdd(&cnt, nz);
        __syncthreads();
        if (threadIdx.x == 0) g_is64 = (cnt < 8) ? 1 : 0;
    }
}

__device__ __forceinline__ int edge_val(const void* ei, int idx, int is64) {
    if (is64) return (int)((const long long*)ei)[idx];
    return ((const int*)ei)[idx];
}

__global__ void degree_k(const void* ei) {
    int i = blockIdx.x * blockDim.x + threadIdx.x;
    if (i >= EE) return;
    int is64 = g_is64;
    int dst = edge_val(ei, EE + i, is64);
    atomicAdd(&g_deg[dst], 1);
}

// ---------------- parallel scan over (deg[i]+1) ----------------------------
__global__ void scan_part() {
    int t = threadIdx.x, lane = t & 31, w = t >> 5;
    int i = blockIdx.x * 256 + t;
    int v = (i < NN) ? g_deg[i] + 1 : 0;
#pragma unroll
    for (int off = 16; off >= 1; off >>= 1) v += __shfl_xor_sync(0xffffffffu, v, off);
    __shared__ int ws[8];
    if (lane == 0) ws[w] = v;
    __syncthreads();
    if (t == 0) {
        int s = 0;
#pragma unroll
        for (int k = 0; k < 8; k++) s += ws[k];
        g_part[blockIdx.x] = s;
    }
}

__global__ void scan_mid() {
    int t = threadIdx.x, lane = t & 31, w = t >> 5;
    int d = (t < NB) ? g_part[t] : 0;
    int v = d;
#pragma unroll
    for (int off = 1; off < 32; off <<= 1) {
        int u = __shfl_up_sync(0xffffffffu, v, off);
        if (lane >= off) v += u;
    }
    __shared__ int ws[8];
    if (lane == 31) ws[w] = v;
    __syncthreads();
    if (w == 0 && lane < 8) {
        int s = ws[lane];
#pragma unroll
        for (int off = 1; off < 8; off <<= 1) {
            int u = __shfl_up_sync(0xffu, s, off);
            if (lane >= off) s += u;
        }
        ws[lane] = s;
    }
    __syncthreads();
    int incl = v + (w > 0 ? ws[w - 1] : 0);
    if (t < NB) g_part[t] = incl - d;
    if (t == 255) g_rowptr[NN] = incl;
}

__global__ void scan_add() {
    int t = threadIdx.x, lane = t & 31, w = t >> 5;
    int i = blockIdx.x * 256 + t;
    int d = (i < NN) ? g_deg[i] + 1 : 0;
    int v = d;
#pragma unroll
    for (int off = 1; off < 32; off <<= 1) {
        int u = __shfl_up_sync(0xffffffffu, v, off);
        if (lane >= off) v += u;
    }
    __shared__ int ws[8];
    if (lane == 31) ws[w] = v;
    __syncthreads();
    if (w == 0 && lane < 8) {
        int s = ws[lane];
#pragma unroll
        for (int off = 1; off < 8; off <<= 1) {
            int u = __shfl_up_sync(0xffu, s, off);
            if (lane >= off) s += u;
        }
        ws[lane] = s;
    }
    __syncthreads();
    int excl = g_part[blockIdx.x] + v - d + (w > 0 ? ws[w - 1] : 0);
    if (i < NN) {
        g_rowptr[i] = excl;
        g_csr[excl] = i;
        g_cursor[i] = excl + 1;
    }
}

__global__ void scatter_k(const void* ei) {
    int i = blockIdx.x * blockDim.x + threadIdx.x;
    if (i >= EE) return;
    int is64 = g_is64;
    int s = edge_val(ei, i, is64);
    int d = edge_val(ei, EE + i, is64);
    int pos = atomicAdd(&g_cursor[d], 1);
    g_csr[pos] = s;
}

// ---------------- conv1 aggregation: warp per node, 8-head online softmax --
__global__ void conv1_agg(const float* __restrict__ att1, const float* __restrict__ b1) {
    int gw   = (blockIdx.x * blockDim.x + threadIdx.x) >> 5;
    int lane = threadIdx.x & 31;
    int d = gw;
    const float* xlbase = g_xlxr;
    const float* xrbase = g_xlxr + (size_t)NN * 128;
    const float4 xr = *(const float4*)&xrbase[(size_t)d * 128 + lane * 4];
    const float4 av = *(const float4*)&att1[lane * 4];
    const float4 bb = *(const float4*)&b1[lane * 4];
    int beg = g_rowptr[d], end = g_rowptr[d + 1];

    float m = -INFINITY, s = 0.f;
    float ax = 0.f, ay = 0.f, az = 0.f, aw = 0.f;

    float4 xl0, xl1;
    xl0 = *(const float4*)&xlbase[(size_t)g_csr[beg] * 128 + lane * 4];
    if (beg + 1 < end)
        xl1 = *(const float4*)&xlbase[(size_t)g_csr[beg + 1] * 128 + lane * 4];
    for (int j = beg; j < end; j++) {
        float4 xl2;
        if (j + 2 < end)
            xl2 = *(const float4*)&xlbase[(size_t)g_csr[j + 2] * 128 + lane * 4];
        float ex = lrelu(xl0.x + xr.x);
        float ey = lrelu(xl0.y + xr.y);
        float ez = lrelu(xl0.z + xr.z);
        float ew = lrelu(xl0.w + xr.w);
        float p = ex * av.x + ey * av.y + ez * av.z + ew * av.w;
        p += __shfl_xor_sync(0xffffffffu, p, 1);
        p += __shfl_xor_sync(0xffffffffu, p, 2);
        float mn = fmaxf(m, p);
        float f  = __expf(m - mn);
        float wt = __expf(p - mn);
        s  = s * f + wt;
        ax = ax * f + xl0.x * wt;
        ay = ay * f + xl0.y * wt;
        az = az * f + xl0.z * wt;
        aw = aw * f + xl0.w * wt;
        m = mn;
        xl0 = xl1; xl1 = xl2;
    }
    float inv = 1.f / s;
    float4 o;
    o.x = elu1(ax * inv + bb.x);
    o.y = elu1(ay * inv + bb.y);
    o.z = elu1(az * inv + bb.z);
    o.w = elu1(aw * inv + bb.w);
    *(float4*)&g_h1[(size_t)d * 128 + lane * 4] = o;
}

// ---------------- conv2 transforms -----------------------------------------
__global__ void conv2_transform(const float* __restrict__ h,
                                const float* __restrict__ Wl2,
                                const float* __restrict__ Wr2) {
    __shared__ float sw[128 * 32];
    __shared__ float sh[8][128];
    int t = threadIdx.x;
    for (int i = t; i < 128 * 16; i += 256) {
        int k = i >> 4, c = i & 15;
        sw[k * 32 + c]      = Wl2[i];
        sw[k * 32 + 16 + c] = Wr2[i];
    }
    int row0 = blockIdx.x * 8;
    for (int i = t; i < 8 * 128; i += 256) {
        int r = i >> 7;
        sh[r][i & 127] = h[(size_t)(row0 + r) * 128 + (i & 127)];
    }
    __syncthreads();
    int warp = t >> 5, lane = t & 31;
    int row = row0 + warp;
    float acc = 0.f;
#pragma unroll
    for (int k = 0; k < 128; k++) acc += sh[warp][k] * sw[k * 32 + lane];
    g_hlr[(size_t)row * 32 + lane] = acc;
}

// ---------------- conv2 aggregation + log_softmax ---------------------------
__global__ void conv2_agg(const float* __restrict__ att2, const float* __restrict__ b2,
                          float* __restrict__ out) {
    int tid = blockIdx.x * blockDim.x + threadIdx.x;
    int d = tid >> 4;
    int l = tid & 15;
    unsigned hm = 0xFFFFu << (((threadIdx.x & 31) >> 4) * 16);

    float xr = g_hlr[(size_t)d * 32 + 16 + l];
    float a  = att2[l];
    int beg = g_rowptr[d], end = g_rowptr[d + 1];

    float m = -INFINITY, s = 0.f, acc = 0.f;
    int src = g_csr[beg];
    float xl = g_hlr[(size_t)src * 32 + l];
    for (int j = beg; j < end; j++) {
        float xln = 0.f;
        if (j + 1 < end) {
            int nsrc = g_csr[j + 1];
            xln = g_hlr[(size_t)nsrc * 32 + l];
        }
        float p = lrelu(xl + xr) * a;
        p += __shfl_xor_sync(hm, p, 1);
        p += __shfl_xor_sync(hm, p, 2);
        p += __shfl_xor_sync(hm, p, 4);
        p += __shfl_xor_sync(hm, p, 8);
        float mn = fmaxf(m, p);
        float f  = __expf(m - mn);
        float w  = __expf(p - mn);
        s   = s * f + w;
        acc = acc * f + xl * w;
        m = mn;
        xl = xln;
    }
    float v = acc / s + b2[l];
    float mm = v;
#pragma unroll
    for (int k = 8; k >= 1; k >>= 1) mm = fmaxf(mm, __shfl_xor_sync(hm, mm, k));
    float pe = expf(v - mm);
    float ss = pe;
#pragma unroll
    for (int k = 8; k >= 1; k >>= 1) ss += __shfl_xor_sync(hm, ss, k);
    out[(size_t)d * 16 + l] = v - mm - logf(ss);
}

// ---------------- side stream (created at static init) ---------------------
static cudaStream_t s_csr = 0;
static cudaEvent_t  ev_fork = 0, ev_join = 0;
namespace {
struct StreamInit {
    StreamInit() {
        cudaStreamCreateWithFlags(&s_csr, cudaStreamNonBlocking);
        cudaEventCreateWithFlags(&ev_fork, cudaEventDisableTiming);
        cudaEventCreateWithFlags(&ev_join, cudaEventDisableTiming);
    }
} s_init;
}

// ---------------- launch ----------------
extern "C" void kernel_launch(void* const* d_in, const int* in_sizes, int n_in,
                              void* d_out, int out_size) {
    const float* x    = (const float*)d_in[0];
    const void*  ei   = d_in[1];
    const float* Wl1  = (const float*)d_in[2];
    const float* Wr1  = (const float*)d_in[3];
    const float* att1 = (const float*)d_in[4];
    const float* b1   = (const float*)d_in[5];
    const float* Wk   = (const float*)d_in[6];
    const float* bk   = (const float*)d_in[7];
    const float* Wl2  = (const float*)d_in[8];
    const float* Wr2  = (const float*)d_in[9];
    const float* att2 = (const float*)d_in[10];
    const float* b2   = (const float*)d_in[11];
    float* out = (float*)d_out;

    float *xlxr, *h1, *h2;
    cudaGetSymbolAddress((void**)&xlxr, g_xlxr);
    cudaGetSymbolAddress((void**)&h1, g_h1);
    cudaGetSymbolAddress((void**)&h2, g_h2);
    float* xl = xlxr;
    float* xr = xlxr + (size_t)NN * 128;

    // weight hi/lo images (5 matrices)
    wconv<<<5, 128>>>(Wl1, Wr1, Wk, Wk + 128 * 128, Wk + 2 * 128 * 128);

    // deg=0 + dtype detect
    init_detect<<<NB, 256>>>(ei);

    // ---- fork: CSR build on side stream, conv1 GEMM on main stream ----
    cudaEventRecord(ev_fork, 0);
    cudaStreamWaitEvent(s_csr, ev_fork, 0);

    degree_k <<<(EE + 255) / 256, 256, 0, s_csr>>>(ei);
    scan_part<<<NB, 256, 0, s_csr>>>();
    scan_mid <<<1, 256, 0, s_csr>>>();
    scan_add <<<NB, 256, 0, s_csr>>>();
    scatter_k<<<(EE + 255) / 256, 256, 0, s_csr>>>(ei);
    cudaEventRecord(ev_join, s_csr);

    // conv1 xl+xr transforms (tensor cores, overlaps CSR build)
    mma_gemm<<<dim3(GX64, 4), 128>>>(x, 0, 1, xl, xr, nullptr, 0);

    // ---- join ----
    cudaStreamWaitEvent(0, ev_join, 0);

    // conv1 aggregation (+elu) -> g_h1
    conv1_agg<<<NN / 8, 256>>>(att1, b1);

    // knowledge layers (tensor cores, bias + elu fused)
    mma_gemm<<<dim3(GX64, 2), 128>>>(h1, 2, 2, h2, h2, bk,       1);
    mma_gemm<<<dim3(GX64, 2), 128>>>(h2, 3, 3, h1, h1, bk + 128, 1);
    mma_gemm<<<dim3(GX64, 2), 128>>>(h1, 4, 4, h2, h2, bk + 256, 1);

    // conv2 transforms -> g_hlr
    conv2_transform<<<NN / 8, 256>>>(h2, Wl2, Wr2);

    // conv2 aggregation + log_softmax -> out
    conv2_agg<<<NN / 16, 256>>>(att2, b2, out);
}

// round 9
// speedup vs baseline: 1.2397x; 1.0610x over previous
#include <cuda_runtime.h>
#include <cuda_bf16.h>
#include <math.h>
#include <stdint.h>

#define NN 50000
#define EE 800000
#define ET 850000   // EE + NN self loops
#define NB 196      // ceil(NN/256)
#define GX64 782    // ceil(NN/64)
#define GPAD 136    // padded row: 136 bf16 = 272B (conflict-free ldmatrix)
#define SMEM_MMA_SZ (2 * 128 * GPAD * 2)   // 69632 B: B hi + lo images

// ---------------- scratch (static device allocations only) ----------------
__device__ float g_xlxr[(size_t)NN * 256];   // [0:N*128)=xl dense, [N*128:)=xr dense
__device__ float g_h1[(size_t)NN * 128];
__device__ float g_h2[(size_t)NN * 128];
__device__ float g_hlr[(size_t)NN * 32];
__device__ int   g_deg[NN];
__device__ int   g_rowptr[NN + 1];
__device__ int   g_cursor[NN];
__device__ int   g_csr[ET];
__device__ int   g_part[256];
__device__ int   g_is64;
// weight images: [matrix 0..4][hi/lo] as [k][n] rows padded to 272B
__device__ __align__(16) __nv_bfloat16 g_wimg[5][2][128 * GPAD];

__device__ __forceinline__ float lrelu(float x) { return x > 0.f ? x : 0.2f * x; }
__device__ __forceinline__ float elu1 (float x) { return x > 0.f ? x : expm1f(x); }

__device__ __forceinline__ uint32_t smem_u32(const void* p) {
    uint32_t a;
    asm("{ .reg .u64 t; cvta.to.shared.u64 t, %1; cvt.u32.u64 %0, t; }"
        : "=r"(a) : "l"(p));
    return a;
}
__device__ __forceinline__ uint32_t pk2(__nv_bfloat16 a, __nv_bfloat16 b) {
    return (uint32_t)__bfloat16_as_ushort(a) | ((uint32_t)__bfloat16_as_ushort(b) << 16);
}
// split float2 into bf16x2 hi + bf16x2 lo (residual)
__device__ __forceinline__ void split2(float2 f, uint32_t& h, uint32_t& l) {
    __nv_bfloat16 hx = __float2bfloat16_rn(f.x);
    __nv_bfloat16 hy = __float2bfloat16_rn(f.y);
    float rx = f.x - __bfloat162float(hx);
    float ry = f.y - __bfloat162float(hy);
    h = pk2(hx, hy);
    l = pk2(__float2bfloat16_rn(rx), __float2bfloat16_rn(ry));
}

__device__ __forceinline__ void ldsm_x4t(uint32_t& r0, uint32_t& r1,
                                         uint32_t& r2, uint32_t& r3, uint32_t addr) {
    asm volatile("ldmatrix.sync.aligned.m8n8.x4.trans.shared.b16 {%0,%1,%2,%3}, [%4];"
        : "=r"(r0), "=r"(r1), "=r"(r2), "=r"(r3) : "r"(addr));
}
__device__ __forceinline__ void mma16816(float* d, const uint32_t* a,
                                         uint32_t b0, uint32_t b1) {
    asm volatile(
        "mma.sync.aligned.m16n8k16.row.col.f32.bf16.bf16.f32 "
        "{%0,%1,%2,%3}, {%4,%5,%6,%7}, {%8,%9}, {%0,%1,%2,%3};"
        : "+f"(d[0]), "+f"(d[1]), "+f"(d[2]), "+f"(d[3])
        : "r"(a[0]), "r"(a[1]), "r"(a[2]), "r"(a[3]), "r"(b0), "r"(b1));
}

// ---------------- weight split kernel: W[k][n] -> hi/lo images --------------
__global__ void wconv(const float* __restrict__ w0, const float* __restrict__ w1,
                      const float* __restrict__ w2, const float* __restrict__ w3,
                      const float* __restrict__ w4) {
    int b = blockIdx.x;
    const float* W = (b == 0) ? w0 : (b == 1) ? w1 : (b == 2) ? w2 : (b == 3) ? w3 : w4;
    __nv_bfloat16* hi = g_wimg[b][0];
    __nv_bfloat16* lo = g_wimg[b][1];
    int n = threadIdx.x;   // 0..127
    for (int k = 0; k < 128; k++) {
        float v = W[(size_t)k * 128 + n];
        __nv_bfloat16 h = __float2bfloat16_rn(v);
        __nv_bfloat16 l = __float2bfloat16_rn(v - __bfloat162float(h));
        hi[k * GPAD + n] = h;
        lo[k * GPAD + n] = l;
    }
}

// ---------------- tensor-core GEMM: C[NN,128] = A[NN,128] @ W --------------
// bf16 hi/lo split, 3 mma passes, fp32 accum. Full-N blocks: 64(M)x128(N),
// 128 threads. grid=(782, nmat). mat=blockIdx.y selects (img, C).
__global__ void __launch_bounds__(128) mma_gemm(
    const float* __restrict__ A, int i0, int i1,
    float* __restrict__ C0, float* __restrict__ C1,
    const float* __restrict__ bias, int act) {
    extern __shared__ __align__(16) __nv_bfloat16 sB[];   // hi[128*GPAD] | lo[128*GPAD]
    const int t = threadIdx.x, lane = t & 31, wid = t >> 5;
    const int mat = blockIdx.y;
    const int img = mat ? i1 : i0;
    float* C = mat ? C1 : C0;
    const int m0 = blockIdx.x * 64 + wid * 16;

    // stage B hi+lo images: one contiguous 69632B copy (4352 uint4)
    {
        const uint4* src = (const uint4*)&g_wimg[img][0][0];
        uint4* dst = (uint4*)sB;
#pragma unroll
        for (int i = 0; i < 34; i++) dst[t + i * 128] = src[t + i * 128];
    }
    __syncthreads();

    const int g  = lane >> 2;        // fragment row group 0..7
    const int cp = (lane & 3) * 2;   // fragment col pair
    const float* Ar0 = A + (size_t)(m0 + g) * 128;
    const float* Ar8 = A + (size_t)(m0 + g + 8) * 128;
    const bool v0 = (m0 + g) < NN;
    const bool v8 = (m0 + g + 8) < NN;

    // ldmatrix per-thread address pieces
    const int bi   = lane >> 3;
    const int brow = (lane & 7) + (bi & 1) * 8;
    const int bcol = (bi >> 1) * 8;
    const uint32_t sbH = smem_u32(sB);
    const uint32_t sbL = sbH + 128 * GPAD * 2;

    float acc[16][4];
#pragma unroll
    for (int i = 0; i < 16; i++)
#pragma unroll
        for (int j = 0; j < 4; j++) acc[i][j] = 0.f;

    for (int ks = 0; ks < 8; ks++) {
        const int k0 = ks * 16;
        // A fragment straight from global, split hi/lo (once per block now)
        float2 f0 = v0 ? *(const float2*)(Ar0 + k0 + cp)     : make_float2(0.f, 0.f);
        float2 f1 = v8 ? *(const float2*)(Ar8 + k0 + cp)     : make_float2(0.f, 0.f);
        float2 f2 = v0 ? *(const float2*)(Ar0 + k0 + cp + 8) : make_float2(0.f, 0.f);
        float2 f3 = v8 ? *(const float2*)(Ar8 + k0 + cp + 8) : make_float2(0.f, 0.f);
        uint32_t ah[4], al[4];
        split2(f0, ah[0], al[0]);
        split2(f1, ah[1], al[1]);
        split2(f2, ah[2], al[2]);
        split2(f3, ah[3], al[3]);

        const uint32_t rowoff = (uint32_t)((k0 + brow) * GPAD + bcol) * 2;
#pragma unroll
        for (int ng = 0; ng < 8; ng++) {
            uint32_t bh0, bh1, bh2, bh3, bl0, bl1, bl2, bl3;
            ldsm_x4t(bh0, bh1, bh2, bh3, sbH + rowoff + ng * 32);
            ldsm_x4t(bl0, bl1, bl2, bl3, sbL + rowoff + ng * 32);
            mma16816(acc[2 * ng],     ah, bh0, bh1);
            mma16816(acc[2 * ng + 1], ah, bh2, bh3);
            mma16816(acc[2 * ng],     ah, bl0, bl1);
            mma16816(acc[2 * ng + 1], ah, bl2, bl3);
            mma16816(acc[2 * ng],     al, bh0, bh1);
            mma16816(acc[2 * ng + 1], al, bh2, bh3);
        }
    }

    // epilogue
    const int r0w = m0 + g, r8w = m0 + g + 8;
#pragma unroll
    for (int nt = 0; nt < 16; nt++) {
        int gc = nt * 8 + cp;
        float v00 = acc[nt][0], v01 = acc[nt][1];
        float v10 = acc[nt][2], v11 = acc[nt][3];
        if (bias) {
            float b0v = bias[gc], b1v = bias[gc + 1];
            v00 += b0v; v01 += b1v; v10 += b0v; v11 += b1v;
        }
        if (act == 1) { v00 = elu1(v00); v01 = elu1(v01); v10 = elu1(v10); v11 = elu1(v11); }
        if (v0) *(float2*)&C[(size_t)r0w * 128 + gc] = make_float2(v00, v01);
        if (v8) *(float2*)&C[(size_t)r8w * 128 + gc] = make_float2(v10, v11);
    }
}

// ---------------- init deg=0 + dtype detect (block 0) ----------------------
__global__ void init_detect(const void* ei) {
    int i = blockIdx.x * blockDim.x + threadIdx.x;
    if (i < NN) g_deg[i] = 0;
    if (blockIdx.x == 0) {
        __shared__ int cnt;
        if (threadIdx.x == 0) cnt = 0;
        __syncthreads();
        const unsigned* p = (const unsigned*)ei;
        int nz = 0;
        for (int k = threadIdx.x; k < 2048; k += 256)
            if (p[2 * k + 1] != 0u) nz++;
        if (nz) atomicAdd(&cnt, nz);
        __syncthreads();
        if (threadIdx.x == 0) g_is64 = (cnt < 8) ? 1 : 0;
    }
}

__device__ __forceinline__ int edge_val(const void* ei, int idx, int is64) {
    if (is64) return (int)((const long long*)ei)[idx];
    return ((const int*)ei)[idx];
}

__global__ void degree_k(const void* ei) {
    int i = blockIdx.x * blockDim.x + threadIdx.x;
    if (i >= EE) return;
    int is64 = g_is64;
    int dst = edge_val(ei, EE + i, is64);
    atomicAdd(&g_deg[dst], 1);
}

// ---------------- parallel scan over (deg[i]+1) ----------------------------
__global__ void scan_part() {
    int t = threadIdx.x, lane = t & 31, w = t >> 5;
    int i = blockIdx.x * 256 + t;
    int v = (i < NN) ? g_deg[i] + 1 : 0;
#pragma unroll
    for (int off = 16; off >= 1; off >>= 1) v += __shfl_xor_sync(0xffffffffu, v, off);
    __shared__ int ws[8];
    if (lane == 0) ws[w] = v;
    __syncthreads();
    if (t == 0) {
        int s = 0;
#pragma unroll
        for (int k = 0; k < 8; k++) s += ws[k];
        g_part[blockIdx.x] = s;
    }
}

__global__ void scan_mid() {
    int t = threadIdx.x, lane = t & 31, w = t >> 5;
    int d = (t < NB) ? g_part[t] : 0;
    int v = d;
#pragma unroll
    for (int off = 1; off < 32; off <<= 1) {
        int u = __shfl_up_sync(0xffffffffu, v, off);
        if (lane >= off) v += u;
    }
    __shared__ int ws[8];
    if (lane == 31) ws[w] = v;
    __syncthreads();
    if (w == 0 && lane < 8) {
        int s = ws[lane];
#pragma unroll
        for (int off = 1; off < 8; off <<= 1) {
            int u = __shfl_up_sync(0xffu, s, off);
            if (lane >= off) s += u;
        }
        ws[lane] = s;
    }
    __syncthreads();
    int incl = v + (w > 0 ? ws[w - 1] : 0);
    if (t < NB) g_part[t] = incl - d;
    if (t == 255) g_rowptr[NN] = incl;
}

__global__ void scan_add() {
    int t = threadIdx.x, lane = t & 31, w = t >> 5;
    int i = blockIdx.x * 256 + t;
    int d = (i < NN) ? g_deg[i] + 1 : 0;
    int v = d;
#pragma unroll
    for (int off = 1; off < 32; off <<= 1) {
        int u = __shfl_up_sync(0xffffffffu, v, off);
        if (lane >= off) v += u;
    }
    __shared__ int ws[8];
    if (lane == 31) ws[w] = v;
    __syncthreads();
    if (w == 0 && lane < 8) {
        int s = ws[lane];
#pragma unroll
        for (int off = 1; off < 8; off <<= 1) {
            int u = __shfl_up_sync(0xffu, s, off);
            if (lane >= off) s += u;
        }
        ws[lane] = s;
    }
    __syncthreads();
    int excl = g_part[blockIdx.x] + v - d + (w > 0 ? ws[w - 1] : 0);
    if (i < NN) {
        g_rowptr[i] = excl;
        g_csr[excl] = i;
        g_cursor[i] = excl + 1;
    }
}

__global__ void scatter_k(const void* ei) {
    int i = blockIdx.x * blockDim.x + threadIdx.x;
    if (i >= EE) return;
    int is64 = g_is64;
    int s = edge_val(ei, i, is64);
    int d = edge_val(ei, EE + i, is64);
    int pos = atomicAdd(&g_cursor[d], 1);
    g_csr[pos] = s;
}

// ---------------- conv1 aggregation: warp per node, 8-head online softmax --
__global__ void conv1_agg(const float* __restrict__ att1, const float* __restrict__ b1) {
    int gw   = (blockIdx.x * blockDim.x + threadIdx.x) >> 5;
    int lane = threadIdx.x & 31;
    int d = gw;
    const float* xlbase = g_xlxr;
    const float* xrbase = g_xlxr + (size_t)NN * 128;
    const float4 xr = *(const float4*)&xrbase[(size_t)d * 128 + lane * 4];
    const float4 av = *(const float4*)&att1[lane * 4];
    const float4 bb = *(const float4*)&b1[lane * 4];
    int beg = g_rowptr[d], end = g_rowptr[d + 1];

    float m = -INFINITY, s = 0.f;
    float ax = 0.f, ay = 0.f, az = 0.f, aw = 0.f;

    float4 xl0, xl1;
    xl0 = *(const float4*)&xlbase[(size_t)g_csr[beg] * 128 + lane * 4];
    if (beg + 1 < end)
        xl1 = *(const float4*)&xlbase[(size_t)g_csr[beg + 1] * 128 + lane * 4];
    for (int j = beg; j < end; j++) {
        float4 xl2;
        if (j + 2 < end)
            xl2 = *(const float4*)&xlbase[(size_t)g_csr[j + 2] * 128 + lane * 4];
        float ex = lrelu(xl0.x + xr.x);
        float ey = lrelu(xl0.y + xr.y);
        float ez = lrelu(xl0.z + xr.z);
        float ew = lrelu(xl0.w + xr.w);
        float p = ex * av.x + ey * av.y + ez * av.z + ew * av.w;
        p += __shfl_xor_sync(0xffffffffu, p, 1);
        p += __shfl_xor_sync(0xffffffffu, p, 2);
        float mn = fmaxf(m, p);
        float f  = __expf(m - mn);
        float wt = __expf(p - mn);
        s  = s * f + wt;
        ax = ax * f + xl0.x * wt;
        ay = ay * f + xl0.y * wt;
        az = az * f + xl0.z * wt;
        aw = aw * f + xl0.w * wt;
        m = mn;
        xl0 = xl1; xl1 = xl2;
    }
    float inv = 1.f / s;
    float4 o;
    o.x = elu1(ax * inv + bb.x);
    o.y = elu1(ay * inv + bb.y);
    o.z = elu1(az * inv + bb.z);
    o.w = elu1(aw * inv + bb.w);
    *(float4*)&g_h1[(size_t)d * 128 + lane * 4] = o;
}

// ---------------- conv2 transforms -----------------------------------------
__global__ void conv2_transform(const float* __restrict__ h,
                                const float* __restrict__ Wl2,
                                const float* __restrict__ Wr2) {
    __shared__ float sw[128 * 32];
    __shared__ float sh[8][128];
    int t = threadIdx.x;
    for (int i = t; i < 128 * 16; i += 256) {
        int k = i >> 4, c = i & 15;
        sw[k * 32 + c]      = Wl2[i];
        sw[k * 32 + 16 + c] = Wr2[i];
    }
    int row0 = blockIdx.x * 8;
    for (int i = t; i < 8 * 128; i += 256) {
        int r = i >> 7;
        sh[r][i & 127] = h[(size_t)(row0 + r) * 128 + (i & 127)];
    }
    __syncthreads();
    int warp = t >> 5, lane = t & 31;
    int row = row0 + warp;
    float acc = 0.f;
#pragma unroll
    for (int k = 0; k < 128; k++) acc += sh[warp][k] * sw[k * 32 + lane];
    g_hlr[(size_t)row * 32 + lane] = acc;
}

// ---------------- conv2 aggregation + log_softmax ---------------------------
__global__ void conv2_agg(const float* __restrict__ att2, const float* __restrict__ b2,
                          float* __restrict__ out) {
    int tid = blockIdx.x * blockDim.x + threadIdx.x;
    int d = tid >> 4;
    int l = tid & 15;
    unsigned hm = 0xFFFFu << (((threadIdx.x & 31) >> 4) * 16);

    float xr = g_hlr[(size_t)d * 32 + 16 + l];
    float a  = att2[l];
    int beg = g_rowptr[d], end = g_rowptr[d + 1];

    float m = -INFINITY, s = 0.f, acc = 0.f;
    int src = g_csr[beg];
    float xl = g_hlr[(size_t)src * 32 + l];
    for (int j = beg; j < end; j++) {
        float xln = 0.f;
        if (j + 1 < end) {
            int nsrc = g_csr[j + 1];
            xln = g_hlr[(size_t)nsrc * 32 + l];
        }
        float p = lrelu(xl + xr) * a;
        p += __shfl_xor_sync(hm, p, 1);
        p += __shfl_xor_sync(hm, p, 2);
        p += __shfl_xor_sync(hm, p, 4);
        p += __shfl_xor_sync(hm, p, 8);
        float mn = fmaxf(m, p);
        float f  = __expf(m - mn);
        float w  = __expf(p - mn);
        s   = s * f + w;
        acc = acc * f + xl * w;
        m = mn;
        xl = xln;
    }
    float v = acc / s + b2[l];
    float mm = v;
#pragma unroll
    for (int k = 8; k >= 1; k >>= 1) mm = fmaxf(mm, __shfl_xor_sync(hm, mm, k));
    float pe = expf(v - mm);
    float ss = pe;
#pragma unroll
    for (int k = 8; k >= 1; k >>= 1) ss += __shfl_xor_sync(hm, ss, k);
    out[(size_t)d * 16 + l] = v - mm - logf(ss);
}

// ---------------- side stream (created at static init) ---------------------
static cudaStream_t s_csr = 0;
static cudaEvent_t  ev_fork = 0, ev_join = 0;
namespace {
struct StreamInit {
    StreamInit() {
        cudaStreamCreateWithFlags(&s_csr, cudaStreamNonBlocking);
        cudaEventCreateWithFlags(&ev_fork, cudaEventDisableTiming);
        cudaEventCreateWithFlags(&ev_join, cudaEventDisableTiming);
    }
} s_init;
}

// ---------------- launch ----------------
extern "C" void kernel_launch(void* const* d_in, const int* in_sizes, int n_in,
                              void* d_out, int out_size) {
    const float* x    = (const float*)d_in[0];
    const void*  ei   = d_in[1];
    const float* Wl1  = (const float*)d_in[2];
    const float* Wr1  = (const float*)d_in[3];
    const float* att1 = (const float*)d_in[4];
    const float* b1   = (const float*)d_in[5];
    const float* Wk   = (const float*)d_in[6];
    const float* bk   = (const float*)d_in[7];
    const float* Wl2  = (const float*)d_in[8];
    const float* Wr2  = (const float*)d_in[9];
    const float* att2 = (const float*)d_in[10];
    const float* b2   = (const float*)d_in[11];
    float* out = (float*)d_out;

    cudaFuncSetAttribute(mma_gemm, cudaFuncAttributeMaxDynamicSharedMemorySize, SMEM_MMA_SZ);

    float *xlxr, *h1, *h2;
    cudaGetSymbolAddress((void**)&xlxr, g_xlxr);
    cudaGetSymbolAddress((void**)&h1, g_h1);
    cudaGetSymbolAddress((void**)&h2, g_h2);
    float* xl = xlxr;
    float* xr = xlxr + (size_t)NN * 128;

    // 1: weight hi/lo images (5 matrices)
    wconv<<<5, 128>>>(Wl1, Wr1, Wk, Wk + 128 * 128, Wk + 2 * 128 * 128);
    // 2: deg=0 + dtype detect
    init_detect<<<NB, 256>>>(ei);

    // ---- fork: CSR build on side stream, conv1 GEMM on main stream ----
    cudaEventRecord(ev_fork, 0);
    cudaStreamWaitEvent(s_csr, ev_fork, 0);

    // 3: degrees (side stream)
    degree_k <<<(EE + 255) / 256, 256, 0, s_csr>>>(ei);
    // 4: conv1 xl+xr transforms (PROFILED SLOT — tensor cores, overlaps CSR)
    mma_gemm<<<dim3(GX64, 2), 128, SMEM_MMA_SZ>>>(x, 0, 1, xl, xr, nullptr, 0);
    // 5-8: rest of CSR build (side stream)
    scan_part<<<NB, 256, 0, s_csr>>>();
    scan_mid <<<1, 256, 0, s_csr>>>();
    scan_add <<<NB, 256, 0, s_csr>>>();
    scatter_k<<<(EE + 255) / 256, 256, 0, s_csr>>>(ei);
    cudaEventRecord(ev_join, s_csr);

    // ---- join ----
    cudaStreamWaitEvent(0, ev_join, 0);

    // conv1 aggregation (+elu) -> g_h1
    conv1_agg<<<NN / 8, 256>>>(att1, b1);

    // knowledge layers (tensor cores, bias + elu fused)
    mma_gemm<<<dim3(GX64, 1), 128, SMEM_MMA_SZ>>>(h1, 2, 2, h2, h2, bk,       1);
    mma_gemm<<<dim3(GX64, 1), 128, SMEM_MMA_SZ>>>(h2, 3, 3, h1, h1, bk + 128, 1);
    mma_gemm<<<dim3(GX64, 1), 128, SMEM_MMA_SZ>>>(h1, 4, 4, h2, h2, bk + 256, 1);

    // conv2 transforms -> g_hlr
    conv2_transform<<<NN / 8, 256>>>(h2, Wl2, Wr2);

    // conv2 aggregation + log_softmax -> out
    conv2_agg<<<NN / 16, 256>>>(att2, b2, out);
}

// round 10
// speedup vs baseline: 1.2551x; 1.0125x over previous
#include <cuda_runtime.h>
#include <cuda_bf16.h>
#include <math.h>
#include <stdint.h>

#define NN 50000
#define EE 800000
#define ET 850000   // EE + NN self loops
#define NB 196      // ceil(NN/256)
#define GX128 391   // ceil(NN/128)
#define GPAD 136    // padded row: 136 bf16 = 272B (conflict-free ldmatrix)
#define SMEM_MMA_SZ (2 * 128 * GPAD * 2)   // 69632 B: B hi + lo images

// ---------------- scratch (static device allocations only) ----------------
__device__ float g_xlxr[(size_t)NN * 256];   // [0:N*128)=xl dense, [N*128:)=xr dense
__device__ float g_h1[(size_t)NN * 128];
__device__ float g_h2[(size_t)NN * 128];
__device__ float g_hlr[(size_t)NN * 32];
__device__ int   g_deg[NN];
__device__ int   g_rowptr[NN + 1];
__device__ int   g_cursor[NN];
__device__ int   g_csr[ET];
__device__ int   g_part[256];
__device__ int   g_is64;
// weight images: [matrix 0..4][hi/lo] as [k][n] rows padded to 272B
__device__ __align__(16) __nv_bfloat16 g_wimg[5][2][128 * GPAD];

__device__ __forceinline__ float lrelu(float x) { return x > 0.f ? x : 0.2f * x; }
__device__ __forceinline__ float elu1 (float x) { return x > 0.f ? x : expm1f(x); }

__device__ __forceinline__ uint32_t smem_u32(const void* p) {
    uint32_t a;
    asm("{ .reg .u64 t; cvta.to.shared.u64 t, %1; cvt.u32.u64 %0, t; }"
        : "=r"(a) : "l"(p));
    return a;
}
__device__ __forceinline__ uint32_t pk2(__nv_bfloat16 a, __nv_bfloat16 b) {
    return (uint32_t)__bfloat16_as_ushort(a) | ((uint32_t)__bfloat16_as_ushort(b) << 16);
}
// split float2 into bf16x2 hi + bf16x2 lo (residual)
__device__ __forceinline__ void split2(float2 f, uint32_t& h, uint32_t& l) {
    __nv_bfloat16 hx = __float2bfloat16_rn(f.x);
    __nv_bfloat16 hy = __float2bfloat16_rn(f.y);
    float rx = f.x - __bfloat162float(hx);
    float ry = f.y - __bfloat162float(hy);
    h = pk2(hx, hy);
    l = pk2(__float2bfloat16_rn(rx), __float2bfloat16_rn(ry));
}

__device__ __forceinline__ void ldsm_x4t(uint32_t& r0, uint32_t& r1,
                                         uint32_t& r2, uint32_t& r3, uint32_t addr) {
    asm volatile("ldmatrix.sync.aligned.m8n8.x4.trans.shared.b16 {%0,%1,%2,%3}, [%4];"
        : "=r"(r0), "=r"(r1), "=r"(r2), "=r"(r3) : "r"(addr));
}
__device__ __forceinline__ void mma16816(float* d, const uint32_t* a,
                                         uint32_t b0, uint32_t b1) {
    asm volatile(
        "mma.sync.aligned.m16n8k16.row.col.f32.bf16.bf16.f32 "
        "{%0,%1,%2,%3}, {%4,%5,%6,%7}, {%8,%9}, {%0,%1,%2,%3};"
        : "+f"(d[0]), "+f"(d[1]), "+f"(d[2]), "+f"(d[3])
        : "r"(a[0]), "r"(a[1]), "r"(a[2]), "r"(a[3]), "r"(b0), "r"(b1));
}

// ---------------- weight split kernel: W[k][n] -> hi/lo images --------------
__global__ void wconv(const float* __restrict__ w0, const float* __restrict__ w1,
                      const float* __restrict__ w2, const float* __restrict__ w3,
                      const float* __restrict__ w4) {
    int b = blockIdx.x;
    const float* W = (b == 0) ? w0 : (b == 1) ? w1 : (b == 2) ? w2 : (b == 3) ? w3 : w4;
    __nv_bfloat16* hi = g_wimg[b][0];
    __nv_bfloat16* lo = g_wimg[b][1];
    int n = threadIdx.x;   // 0..127
    for (int k = 0; k < 128; k++) {
        float v = W[(size_t)k * 128 + n];
        __nv_bfloat16 h = __float2bfloat16_rn(v);
        __nv_bfloat16 l = __float2bfloat16_rn(v - __bfloat162float(h));
        hi[k * GPAD + n] = h;
        lo[k * GPAD + n] = l;
    }
}

// ---------------- tensor-core GEMM: C[NN,128] = A[NN,128] @ W --------------
// bf16 hi/lo split, 3 mma passes, fp32 accum. 128(M)x128(N) per 256-thread
// CTA (8 warps x 16 rows). grid=(391, nmat). mat=blockIdx.y selects (img, C).
__global__ void __launch_bounds__(256) mma_gemm(
    const float* __restrict__ A, int i0, int i1,
    float* __restrict__ C0, float* __restrict__ C1,
    const float* __restrict__ bias, int act) {
    extern __shared__ __align__(16) __nv_bfloat16 sB[];   // hi[128*GPAD] | lo[128*GPAD]
    const int t = threadIdx.x, lane = t & 31, wid = t >> 5;
    const int mat = blockIdx.y;
    const int img = mat ? i1 : i0;
    float* C = mat ? C1 : C0;
    const int m0 = blockIdx.x * 128 + wid * 16;

    // stage B hi+lo images: one contiguous 69632B copy (4352 uint4)
    {
        const uint4* src = (const uint4*)&g_wimg[img][0][0];
        uint4* dst = (uint4*)sB;
#pragma unroll
        for (int i = 0; i < 17; i++) dst[t + i * 256] = src[t + i * 256];
    }
    __syncthreads();

    const int g  = lane >> 2;        // fragment row group 0..7
    const int cp = (lane & 3) * 2;   // fragment col pair
    const float* Ar0 = A + (size_t)(m0 + g) * 128;
    const float* Ar8 = A + (size_t)(m0 + g + 8) * 128;
    const bool v0 = (m0 + g) < NN;
    const bool v8 = (m0 + g + 8) < NN;

    // ldmatrix per-thread address pieces
    const int bi   = lane >> 3;
    const int brow = (lane & 7) + (bi & 1) * 8;
    const int bcol = (bi >> 1) * 8;
    const uint32_t sbH = smem_u32(sB);
    const uint32_t sbL = sbH + 128 * GPAD * 2;

    float acc[16][4];
#pragma unroll
    for (int i = 0; i < 16; i++)
#pragma unroll
        for (int j = 0; j < 4; j++) acc[i][j] = 0.f;

    for (int ks = 0; ks < 8; ks++) {
        const int k0 = ks * 16;
        // A fragment straight from global, split hi/lo
        float2 f0 = v0 ? *(const float2*)(Ar0 + k0 + cp)     : make_float2(0.f, 0.f);
        float2 f1 = v8 ? *(const float2*)(Ar8 + k0 + cp)     : make_float2(0.f, 0.f);
        float2 f2 = v0 ? *(const float2*)(Ar0 + k0 + cp + 8) : make_float2(0.f, 0.f);
        float2 f3 = v8 ? *(const float2*)(Ar8 + k0 + cp + 8) : make_float2(0.f, 0.f);
        uint32_t ah[4], al[4];
        split2(f0, ah[0], al[0]);
        split2(f1, ah[1], al[1]);
        split2(f2, ah[2], al[2]);
        split2(f3, ah[3], al[3]);

        const uint32_t rowoff = (uint32_t)((k0 + brow) * GPAD + bcol) * 2;
#pragma unroll
        for (int ng = 0; ng < 8; ng++) {
            uint32_t bh0, bh1, bh2, bh3, bl0, bl1, bl2, bl3;
            ldsm_x4t(bh0, bh1, bh2, bh3, sbH + rowoff + ng * 32);
            ldsm_x4t(bl0, bl1, bl2, bl3, sbL + rowoff + ng * 32);
            mma16816(acc[2 * ng],     ah, bh0, bh1);
            mma16816(acc[2 * ng + 1], ah, bh2, bh3);
            mma16816(acc[2 * ng],     ah, bl0, bl1);
            mma16816(acc[2 * ng + 1], ah, bl2, bl3);
            mma16816(acc[2 * ng],     al, bh0, bh1);
            mma16816(acc[2 * ng + 1], al, bh2, bh3);
        }
    }

    // epilogue
    const int r0w = m0 + g, r8w = m0 + g + 8;
#pragma unroll
    for (int nt = 0; nt < 16; nt++) {
        int gc = nt * 8 + cp;
        float v00 = acc[nt][0], v01 = acc[nt][1];
        float v10 = acc[nt][2], v11 = acc[nt][3];
        if (bias) {
            float b0v = bias[gc], b1v = bias[gc + 1];
            v00 += b0v; v01 += b1v; v10 += b0v; v11 += b1v;
        }
        if (act == 1) { v00 = elu1(v00); v01 = elu1(v01); v10 = elu1(v10); v11 = elu1(v11); }
        if (v0) *(float2*)&C[(size_t)r0w * 128 + gc] = make_float2(v00, v01);
        if (v8) *(float2*)&C[(size_t)r8w * 128 + gc] = make_float2(v10, v11);
    }
}

// ---------------- init deg=0 + dtype detect (block 0) ----------------------
__global__ void init_detect(const void* ei) {
    int i = blockIdx.x * blockDim.x + threadIdx.x;
    if (i < NN) g_deg[i] = 0;
    if (blockIdx.x == 0) {
        __shared__ int cnt;
        if (threadIdx.x == 0) cnt = 0;
        __syncthreads();
        const unsigned* p = (const unsigned*)ei;
        int nz = 0;
        for (int k = threadIdx.x; k < 2048; k += 256)
            if (p[2 * k + 1] != 0u) nz++;
        if (nz) atomicAdd(&cnt, nz);
        __syncthreads();
        if (threadIdx.x == 0) g_is64 = (cnt < 8) ? 1 : 0;
    }
}

__device__ __forceinline__ int edge_val(const void* ei, int idx, int is64) {
    if (is64) return (int)((const long long*)ei)[idx];
    return ((const int*)ei)[idx];
}

__global__ void degree_k(const void* ei) {
    int i = blockIdx.x * blockDim.x + threadIdx.x;
    if (i >= EE) return;
    int is64 = g_is64;
    int dst = edge_val(ei, EE + i, is64);
    atomicAdd(&g_deg[dst], 1);
}

// ---------------- parallel scan over (deg[i]+1) ----------------------------
__global__ void scan_part() {
    int t = threadIdx.x, lane = t & 31, w = t >> 5;
    int i = blockIdx.x * 256 + t;
    int v = (i < NN) ? g_deg[i] + 1 : 0;
#pragma unroll
    for (int off = 16; off >= 1; off >>= 1) v += __shfl_xor_sync(0xffffffffu, v, off);
    __shared__ int ws[8];
    if (lane == 0) ws[w] = v;
    __syncthreads();
    if (t == 0) {
        int s = 0;
#pragma unroll
        for (int k = 0; k < 8; k++) s += ws[k];
        g_part[blockIdx.x] = s;
    }
}

__global__ void scan_mid() {
    int t = threadIdx.x, lane = t & 31, w = t >> 5;
    int d = (t < NB) ? g_part[t] : 0;
    int v = d;
#pragma unroll
    for (int off = 1; off < 32; off <<= 1) {
        int u = __shfl_up_sync(0xffffffffu, v, off);
        if (lane >= off) v += u;
    }
    __shared__ int ws[8];
    if (lane == 31) ws[w] = v;
    __syncthreads();
    if (w == 0 && lane < 8) {
        int s = ws[lane];
#pragma unroll
        for (int off = 1; off < 8; off <<= 1) {
            int u = __shfl_up_sync(0xffu, s, off);
            if (lane >= off) s += u;
        }
        ws[lane] = s;
    }
    __syncthreads();
    int incl = v + (w > 0 ? ws[w - 1] : 0);
    if (t < NB) g_part[t] = incl - d;
    if (t == 255) g_rowptr[NN] = incl;
}

__global__ void scan_add() {
    int t = threadIdx.x, lane = t & 31, w = t >> 5;
    int i = blockIdx.x * 256 + t;
    int d = (i < NN) ? g_deg[i] + 1 : 0;
    int v = d;
#pragma unroll
    for (int off = 1; off < 32; off <<= 1) {
        int u = __shfl_up_sync(0xffffffffu, v, off);
        if (lane >= off) v += u;
    }
    __shared__ int ws[8];
    if (lane == 31) ws[w] = v;
    __syncthreads();
    if (w == 0 && lane < 8) {
        int s = ws[lane];
#pragma unroll
        for (int off = 1; off < 8; off <<= 1) {
            int u = __shfl_up_sync(0xffu, s, off);
            if (lane >= off) s += u;
        }
        ws[lane] = s;
    }
    __syncthreads();
    int excl = g_part[blockIdx.x] + v - d + (w > 0 ? ws[w - 1] : 0);
    if (i < NN) {
        g_rowptr[i] = excl;
        g_csr[excl] = i;
        g_cursor[i] = excl + 1;
    }
}

__global__ void scatter_k(const void* ei) {
    int i = blockIdx.x * blockDim.x + threadIdx.x;
    if (i >= EE) return;
    int is64 = g_is64;
    int s = edge_val(ei, i, is64);
    int d = edge_val(ei, EE + i, is64);
    int pos = atomicAdd(&g_cursor[d], 1);
    g_csr[pos] = s;
}

// ---------------- conv1 aggregation: warp per node, 8-head online softmax --
__global__ void conv1_agg(const float* __restrict__ att1, const float* __restrict__ b1) {
    int gw   = (blockIdx.x * blockDim.x + threadIdx.x) >> 5;
    int lane = threadIdx.x & 31;
    int d = gw;
    const float* xlbase = g_xlxr;
    const float* xrbase = g_xlxr + (size_t)NN * 128;
    const float4 xr = *(const float4*)&xrbase[(size_t)d * 128 + lane * 4];
    const float4 av = *(const float4*)&att1[lane * 4];
    const float4 bb = *(const float4*)&b1[lane * 4];
    int beg = g_rowptr[d], end = g_rowptr[d + 1];

    float m = -INFINITY, s = 0.f;
    float ax = 0.f, ay = 0.f, az = 0.f, aw = 0.f;

    float4 xl0, xl1;
    xl0 = *(const float4*)&xlbase[(size_t)g_csr[beg] * 128 + lane * 4];
    if (beg + 1 < end)
        xl1 = *(const float4*)&xlbase[(size_t)g_csr[beg + 1] * 128 + lane * 4];
    for (int j = beg; j < end; j++) {
        float4 xl2;
        if (j + 2 < end)
            xl2 = *(const float4*)&xlbase[(size_t)g_csr[j + 2] * 128 + lane * 4];
        float ex = lrelu(xl0.x + xr.x);
        float ey = lrelu(xl0.y + xr.y);
        float ez = lrelu(xl0.z + xr.z);
        float ew = lrelu(xl0.w + xr.w);
        float p = ex * av.x + ey * av.y + ez * av.z + ew * av.w;
        p += __shfl_xor_sync(0xffffffffu, p, 1);
        p += __shfl_xor_sync(0xffffffffu, p, 2);
        float mn = fmaxf(m, p);
        float f  = __expf(m - mn);
        float wt = __expf(p - mn);
        s  = s * f + wt;
        ax = ax * f + xl0.x * wt;
        ay = ay * f + xl0.y * wt;
        az = az * f + xl0.z * wt;
        aw = aw * f + xl0.w * wt;
        m = mn;
        xl0 = xl1; xl1 = xl2;
    }
    float inv = 1.f / s;
    float4 o;
    o.x = elu1(ax * inv + bb.x);
    o.y = elu1(ay * inv + bb.y);
    o.z = elu1(az * inv + bb.z);
    o.w = elu1(aw * inv + bb.w);
    *(float4*)&g_h1[(size_t)d * 128 + lane * 4] = o;
}

// ---------------- conv2 transforms -----------------------------------------
__global__ void conv2_transform(const float* __restrict__ h,
                                const float* __restrict__ Wl2,
                                const float* __restrict__ Wr2) {
    __shared__ float sw[128 * 32];
    __shared__ float sh[8][128];
    int t = threadIdx.x;
    for (int i = t; i < 128 * 16; i += 256) {
        int k = i >> 4, c = i & 15;
        sw[k * 32 + c]      = Wl2[i];
        sw[k * 32 + 16 + c] = Wr2[i];
    }
    int row0 = blockIdx.x * 8;
    for (int i = t; i < 8 * 128; i += 256) {
        int r = i >> 7;
        sh[r][i & 127] = h[(size_t)(row0 + r) * 128 + (i & 127)];
    }
    __syncthreads();
    int warp = t >> 5, lane = t & 31;
    int row = row0 + warp;
    float acc = 0.f;
#pragma unroll
    for (int k = 0; k < 128; k++) acc += sh[warp][k] * sw[k * 32 + lane];
    g_hlr[(size_t)row * 32 + lane] = acc;
}

// ---------------- conv2 aggregation + log_softmax ---------------------------
__global__ void conv2_agg(const float* __restrict__ att2, const float* __restrict__ b2,
                          float* __restrict__ out) {
    int tid = blockIdx.x * blockDim.x + threadIdx.x;
    int d = tid >> 4;
    int l = tid & 15;
    unsigned hm = 0xFFFFu << (((threadIdx.x & 31) >> 4) * 16);

    float xr = g_hlr[(size_t)d * 32 + 16 + l];
    float a  = att2[l];
    int beg = g_rowptr[d], end = g_rowptr[d + 1];

    float m = -INFINITY, s = 0.f, acc = 0.f;
    int src = g_csr[beg];
    float xl = g_hlr[(size_t)src * 32 + l];
    for (int j = beg; j < end; j++) {
        float xln = 0.f;
        if (j + 1 < end) {
            int nsrc = g_csr[j + 1];
            xln = g_hlr[(size_t)nsrc * 32 + l];
        }
        float p = lrelu(xl + xr) * a;
        p += __shfl_xor_sync(hm, p, 1);
        p += __shfl_xor_sync(hm, p, 2);
        p += __shfl_xor_sync(hm, p, 4);
        p += __shfl_xor_sync(hm, p, 8);
        float mn = fmaxf(m, p);
        float f  = __expf(m - mn);
        float w  = __expf(p - mn);
        s   = s * f + w;
        acc = acc * f + xl * w;
        m = mn;
        xl = xln;
    }
    float v = acc / s + b2[l];
    float mm = v;
#pragma unroll
    for (int k = 8; k >= 1; k >>= 1) mm = fmaxf(mm, __shfl_xor_sync(hm, mm, k));
    float pe = expf(v - mm);
    float ss = pe;
#pragma unroll
    for (int k = 8; k >= 1; k >>= 1) ss += __shfl_xor_sync(hm, ss, k);
    out[(size_t)d * 16 + l] = v - mm - logf(ss);
}

// ---------------- side stream (created at static init) ---------------------
static cudaStream_t s_csr = 0;
static cudaEvent_t  ev_fork = 0, ev_join = 0;
namespace {
struct StreamInit {
    StreamInit() {
        cudaStreamCreateWithFlags(&s_csr, cudaStreamNonBlocking);
        cudaEventCreateWithFlags(&ev_fork, cudaEventDisableTiming);
        cudaEventCreateWithFlags(&ev_join, cudaEventDisableTiming);
    }
} s_init;
}

// ---------------- launch ----------------
extern "C" void kernel_launch(void* const* d_in, const int* in_sizes, int n_in,
                              void* d_out, int out_size) {
    const float* x    = (const float*)d_in[0];
    const void*  ei   = d_in[1];
    const float* Wl1  = (const float*)d_in[2];
    const float* Wr1  = (const float*)d_in[3];
    const float* att1 = (const float*)d_in[4];
    const float* b1   = (const float*)d_in[5];
    const float* Wk   = (const float*)d_in[6];
    const float* bk   = (const float*)d_in[7];
    const float* Wl2  = (const float*)d_in[8];
    const float* Wr2  = (const float*)d_in[9];
    const float* att2 = (const float*)d_in[10];
    const float* b2   = (const float*)d_in[11];
    float* out = (float*)d_out;

    cudaFuncSetAttribute(mma_gemm, cudaFuncAttributeMaxDynamicSharedMemorySize, SMEM_MMA_SZ);

    float *xlxr, *h1, *h2;
    cudaGetSymbolAddress((void**)&xlxr, g_xlxr);
    cudaGetSymbolAddress((void**)&h1, g_h1);
    cudaGetSymbolAddress((void**)&h2, g_h2);
    float* xl = xlxr;
    float* xr = xlxr + (size_t)NN * 128;

    // 1: weight hi/lo images (5 matrices)
    wconv<<<5, 128>>>(Wl1, Wr1, Wk, Wk + 128 * 128, Wk + 2 * 128 * 128);
    // 2: deg=0 + dtype detect
    init_detect<<<NB, 256>>>(ei);

    // ---- fork: CSR build on side stream, conv1 GEMM on main stream ----
    cudaEventRecord(ev_fork, 0);
    cudaStreamWaitEvent(s_csr, ev_fork, 0);

    // 3: degrees (side stream)
    degree_k <<<(EE + 255) / 256, 256, 0, s_csr>>>(ei);
    // 4: conv1 xl+xr transforms (PROFILED SLOT — tensor cores, overlaps CSR)
    mma_gemm<<<dim3(GX128, 2), 256, SMEM_MMA_SZ>>>(x, 0, 1, xl, xr, nullptr, 0);
    // 5-8: rest of CSR build (side stream)
    scan_part<<<NB, 256, 0, s_csr>>>();
    scan_mid <<<1, 256, 0, s_csr>>>();
    scan_add <<<NB, 256, 0, s_csr>>>();
    scatter_k<<<(EE + 255) / 256, 256, 0, s_csr>>>(ei);
    cudaEventRecord(ev_join, s_csr);

    // ---- join ----
    cudaStreamWaitEvent(0, ev_join, 0);

    // conv1 aggregation (+elu) -> g_h1
    conv1_agg<<<NN / 8, 256>>>(att1, b1);

    // knowledge layers (tensor cores, bias + elu fused)
    mma_gemm<<<dim3(GX128, 1), 256, SMEM_MMA_SZ>>>(h1, 2, 2, h2, h2, bk,       1);
    mma_gemm<<<dim3(GX128, 1), 256, SMEM_MMA_SZ>>>(h2, 3, 3, h1, h1, bk + 128, 1);
    mma_gemm<<<dim3(GX128, 1), 256, SMEM_MMA_SZ>>>(h1, 4, 4, h2, h2, bk + 256, 1);

    // conv2 transforms -> g_hlr
    conv2_transform<<<NN / 8, 256>>>(h2, Wl2, Wr2);

    // conv2 aggregation + log_softmax -> out
    conv2_agg<<<NN / 16, 256>>>(att2, b2, out);
}

// round 11
// speedup vs baseline: 1.3214x; 1.0528x over previous
#include <cuda_runtime.h>
#include <cuda_bf16.h>
#include <math.h>
#include <stdint.h>

#define NN 50000
#define EE 800000
#define ET 850000   // EE + NN self loops
#define NB 196      // ceil(NN/256)
#define GX128 391   // ceil(NN/128)
#define GPAD 136    // padded row: 136 bf16 = 272B (conflict-free ldmatrix)
#define SMEM_MMA_SZ (2 * 128 * GPAD * 2)   // 69632 B: B hi + lo images

// ---------------- scratch (static device allocations only) ----------------
__device__ float g_xlxr[(size_t)NN * 256];   // [0:N*128)=xl dense, [N*128:)=xr dense
__device__ float g_h1[(size_t)NN * 128];
__device__ float g_h2[(size_t)NN * 128];
__device__ float g_hlr[(size_t)NN * 32];
__device__ int   g_deg[NN];
__device__ int   g_rowptr[NN + 1];
__device__ int   g_cursor[NN];
__device__ int   g_csr[ET];
__device__ int   g_part[256];
__device__ int   g_is64;
// weight images: [matrix 0..4][hi/lo] as [k][n] rows padded to 272B
__device__ __align__(16) __nv_bfloat16 g_wimg[5][2][128 * GPAD];

__device__ __forceinline__ float lrelu(float x) { return x > 0.f ? x : 0.2f * x; }
__device__ __forceinline__ float elu1 (float x) { return x > 0.f ? x : expm1f(x); }

__device__ __forceinline__ uint32_t smem_u32(const void* p) {
    uint32_t a;
    asm("{ .reg .u64 t; cvta.to.shared.u64 t, %1; cvt.u32.u64 %0, t; }"
        : "=r"(a) : "l"(p));
    return a;
}
__device__ __forceinline__ uint32_t pk2(__nv_bfloat16 a, __nv_bfloat16 b) {
    return (uint32_t)__bfloat16_as_ushort(a) | ((uint32_t)__bfloat16_as_ushort(b) << 16);
}
// split float2 into bf16x2 hi + bf16x2 lo (residual)
__device__ __forceinline__ void split2(float2 f, uint32_t& h, uint32_t& l) {
    __nv_bfloat16 hx = __float2bfloat16_rn(f.x);
    __nv_bfloat16 hy = __float2bfloat16_rn(f.y);
    float rx = f.x - __bfloat162float(hx);
    float ry = f.y - __bfloat162float(hy);
    h = pk2(hx, hy);
    l = pk2(__float2bfloat16_rn(rx), __float2bfloat16_rn(ry));
}

__device__ __forceinline__ void ldsm_x4t(uint32_t& r0, uint32_t& r1,
                                         uint32_t& r2, uint32_t& r3, uint32_t addr) {
    asm volatile("ldmatrix.sync.aligned.m8n8.x4.trans.shared.b16 {%0,%1,%2,%3}, [%4];"
        : "=r"(r0), "=r"(r1), "=r"(r2), "=r"(r3) : "r"(addr));
}
__device__ __forceinline__ void mma16816(float* d, const uint32_t* a,
                                         uint32_t b0, uint32_t b1) {
    asm volatile(
        "mma.sync.aligned.m16n8k16.row.col.f32.bf16.bf16.f32 "
        "{%0,%1,%2,%3}, {%4,%5,%6,%7}, {%8,%9}, {%0,%1,%2,%3};"
        : "+f"(d[0]), "+f"(d[1]), "+f"(d[2]), "+f"(d[3])
        : "r"(a[0]), "r"(a[1]), "r"(a[2]), "r"(a[3]), "r"(b0), "r"(b1));
}

// ---------------- weight split kernel: W[k][n] -> hi/lo images --------------
__global__ void wconv(const float* __restrict__ w0, const float* __restrict__ w1,
                      const float* __restrict__ w2, const float* __restrict__ w3,
                      const float* __restrict__ w4) {
    int b = blockIdx.x;
    const float* W = (b == 0) ? w0 : (b == 1) ? w1 : (b == 2) ? w2 : (b == 3) ? w3 : w4;
    __nv_bfloat16* hi = g_wimg[b][0];
    __nv_bfloat16* lo = g_wimg[b][1];
    int n = threadIdx.x;   // 0..127
    for (int k = 0; k < 128; k++) {
        float v = W[(size_t)k * 128 + n];
        __nv_bfloat16 h = __float2bfloat16_rn(v);
        __nv_bfloat16 l = __float2bfloat16_rn(v - __bfloat162float(h));
        hi[k * GPAD + n] = h;
        lo[k * GPAD + n] = l;
    }
}

// ---------------- tensor-core GEMM: C[NN,128] = A[NN,128] @ W --------------
// bf16 hi/lo split, 3 mma passes, fp32 accum. 128(M)x128(N) per 256-thread
// CTA, processed as two sequential 64-col halves so acc is only 32 regs.
// grid=(391, nmat). mat=blockIdx.y selects (img, C).
__global__ void __launch_bounds__(256) mma_gemm(
    const float* __restrict__ A, int i0, int i1,
    float* __restrict__ C0, float* __restrict__ C1,
    const float* __restrict__ bias, int act) {
    extern __shared__ __align__(16) __nv_bfloat16 sB[];   // hi[128*GPAD] | lo[128*GPAD]
    const int t = threadIdx.x, lane = t & 31, wid = t >> 5;
    const int mat = blockIdx.y;
    const int img = mat ? i1 : i0;
    float* C = mat ? C1 : C0;
    const int m0 = blockIdx.x * 128 + wid * 16;

    // stage B hi+lo images: one contiguous 69632B copy (4352 uint4)
    {
        const uint4* src = (const uint4*)&g_wimg[img][0][0];
        uint4* dst = (uint4*)sB;
#pragma unroll
        for (int i = 0; i < 17; i++) dst[t + i * 256] = src[t + i * 256];
    }
    __syncthreads();

    const int g  = lane >> 2;        // fragment row group 0..7
    const int cp = (lane & 3) * 2;   // fragment col pair
    const float* Ar0 = A + (size_t)(m0 + g) * 128;
    const float* Ar8 = A + (size_t)(m0 + g + 8) * 128;
    const bool v0 = (m0 + g) < NN;
    const bool v8 = (m0 + g + 8) < NN;

    // ldmatrix per-thread address pieces
    const int bi   = lane >> 3;
    const int brow = (lane & 7) + (bi & 1) * 8;
    const int bcol = (bi >> 1) * 8;
    const uint32_t sbH = smem_u32(sB);
    const uint32_t sbL = sbH + 128 * GPAD * 2;

    const int r0w = m0 + g, r8w = m0 + g + 8;

#pragma unroll
    for (int nh = 0; nh < 2; nh++) {
        const uint32_t hoff = (uint32_t)nh * 128;   // 64 cols * 2 B
        float acc[8][4];
#pragma unroll
        for (int i = 0; i < 8; i++)
#pragma unroll
            for (int j = 0; j < 4; j++) acc[i][j] = 0.f;

        for (int ks = 0; ks < 8; ks++) {
            const int k0 = ks * 16;
            // A fragment from global (L2-hot on 2nd half), split hi/lo
            float2 f0 = v0 ? *(const float2*)(Ar0 + k0 + cp)     : make_float2(0.f, 0.f);
            float2 f1 = v8 ? *(const float2*)(Ar8 + k0 + cp)     : make_float2(0.f, 0.f);
            float2 f2 = v0 ? *(const float2*)(Ar0 + k0 + cp + 8) : make_float2(0.f, 0.f);
            float2 f3 = v8 ? *(const float2*)(Ar8 + k0 + cp + 8) : make_float2(0.f, 0.f);
            uint32_t ah[4], al[4];
            split2(f0, ah[0], al[0]);
            split2(f1, ah[1], al[1]);
            split2(f2, ah[2], al[2]);
            split2(f3, ah[3], al[3]);

            const uint32_t rowoff = (uint32_t)((k0 + brow) * GPAD + bcol) * 2 + hoff;
#pragma unroll
            for (int ng = 0; ng < 4; ng++) {
                uint32_t bh0, bh1, bh2, bh3, bl0, bl1, bl2, bl3;
                ldsm_x4t(bh0, bh1, bh2, bh3, sbH + rowoff + ng * 32);
                ldsm_x4t(bl0, bl1, bl2, bl3, sbL + rowoff + ng * 32);
                mma16816(acc[2 * ng],     ah, bh0, bh1);
                mma16816(acc[2 * ng + 1], ah, bh2, bh3);
                mma16816(acc[2 * ng],     ah, bl0, bl1);
                mma16816(acc[2 * ng + 1], ah, bl2, bl3);
                mma16816(acc[2 * ng],     al, bh0, bh1);
                mma16816(acc[2 * ng + 1], al, bh2, bh3);
            }
        }

        // epilogue for this 64-col half
#pragma unroll
        for (int nt = 0; nt < 8; nt++) {
            int gc = nh * 64 + nt * 8 + cp;
            float v00 = acc[nt][0], v01 = acc[nt][1];
            float v10 = acc[nt][2], v11 = acc[nt][3];
            if (bias) {
                float b0v = bias[gc], b1v = bias[gc + 1];
                v00 += b0v; v01 += b1v; v10 += b0v; v11 += b1v;
            }
            if (act == 1) { v00 = elu1(v00); v01 = elu1(v01); v10 = elu1(v10); v11 = elu1(v11); }
            if (v0) *(float2*)&C[(size_t)r0w * 128 + gc] = make_float2(v00, v01);
            if (v8) *(float2*)&C[(size_t)r8w * 128 + gc] = make_float2(v10, v11);
        }
    }
}

// ---------------- init deg=0 + dtype detect (block 0) ----------------------
__global__ void init_detect(const void* ei) {
    int i = blockIdx.x * blockDim.x + threadIdx.x;
    if (i < NN) g_deg[i] = 0;
    if (blockIdx.x == 0) {
        __shared__ int cnt;
        if (threadIdx.x == 0) cnt = 0;
        __syncthreads();
        const unsigned* p = (const unsigned*)ei;
        int nz = 0;
        for (int k = threadIdx.x; k < 2048; k += 256)
            if (p[2 * k + 1] != 0u) nz++;
        if (nz) atomicAdd(&cnt, nz);
        __syncthreads();
        if (threadIdx.x == 0) g_is64 = (cnt < 8) ? 1 : 0;
    }
}

__device__ __forceinline__ int edge_val(const void* ei, int idx, int is64) {
    if (is64) return (int)((const long long*)ei)[idx];
    return ((const int*)ei)[idx];
}

__global__ void degree_k(const void* ei) {
    int i = blockIdx.x * blockDim.x + threadIdx.x;
    if (i >= EE) return;
    int is64 = g_is64;
    int dst = edge_val(ei, EE + i, is64);
    atomicAdd(&g_deg[dst], 1);
}

// ---------------- parallel scan over (deg[i]+1) ----------------------------
__global__ void scan_part() {
    int t = threadIdx.x, lane = t & 31, w = t >> 5;
    int i = blockIdx.x * 256 + t;
    int v = (i < NN) ? g_deg[i] + 1 : 0;
#pragma unroll
    for (int off = 16; off >= 1; off >>= 1) v += __shfl_xor_sync(0xffffffffu, v, off);
    __shared__ int ws[8];
    if (lane == 0) ws[w] = v;
    __syncthreads();
    if (t == 0) {
        int s = 0;
#pragma unroll
        for (int k = 0; k < 8; k++) s += ws[k];
        g_part[blockIdx.x] = s;
    }
}

__global__ void scan_mid() {
    int t = threadIdx.x, lane = t & 31, w = t >> 5;
    int d = (t < NB) ? g_part[t] : 0;
    int v = d;
#pragma unroll
    for (int off = 1; off < 32; off <<= 1) {
        int u = __shfl_up_sync(0xffffffffu, v, off);
        if (lane >= off) v += u;
    }
    __shared__ int ws[8];
    if (lane == 31) ws[w] = v;
    __syncthreads();
    if (w == 0 && lane < 8) {
        int s = ws[lane];
#pragma unroll
        for (int off = 1; off < 8; off <<= 1) {
            int u = __shfl_up_sync(0xffu, s, off);
            if (lane >= off) s += u;
        }
        ws[lane] = s;
    }
    __syncthreads();
    int incl = v + (w > 0 ? ws[w - 1] : 0);
    if (t < NB) g_part[t] = incl - d;
    if (t == 255) g_rowptr[NN] = incl;
}

__global__ void scan_add() {
    int t = threadIdx.x, lane = t & 31, w = t >> 5;
    int i = blockIdx.x * 256 + t;
    int d = (i < NN) ? g_deg[i] + 1 : 0;
    int v = d;
#pragma unroll
    for (int off = 1; off < 32; off <<= 1) {
        int u = __shfl_up_sync(0xffffffffu, v, off);
        if (lane >= off) v += u;
    }
    __shared__ int ws[8];
    if (lane == 31) ws[w] = v;
    __syncthreads();
    if (w == 0 && lane < 8) {
        int s = ws[lane];
#pragma unroll
        for (int off = 1; off < 8; off <<= 1) {
            int u = __shfl_up_sync(0xffu, s, off);
            if (lane >= off) s += u;
        }
        ws[lane] = s;
    }
    __syncthreads();
    int excl = g_part[blockIdx.x] + v - d + (w > 0 ? ws[w - 1] : 0);
    if (i < NN) {
        g_rowptr[i] = excl;
        g_csr[excl] = i;
        g_cursor[i] = excl + 1;
    }
}

__global__ void scatter_k(const void* ei) {
    int i = blockIdx.x * blockDim.x + threadIdx.x;
    if (i >= EE) return;
    int is64 = g_is64;
    int s = edge_val(ei, i, is64);
    int d = edge_val(ei, EE + i, is64);
    int pos = atomicAdd(&g_cursor[d], 1);
    g_csr[pos] = s;
}

// ---------------- conv1 aggregation: warp per node, 8-head online softmax --
__global__ void conv1_agg(const float* __restrict__ att1, const float* __restrict__ b1) {
    int gw   = (blockIdx.x * blockDim.x + threadIdx.x) >> 5;
    int lane = threadIdx.x & 31;
    int d = gw;
    const float* xlbase = g_xlxr;
    const float* xrbase = g_xlxr + (size_t)NN * 128;
    const float4 xr = *(const float4*)&xrbase[(size_t)d * 128 + lane * 4];
    const float4 av = *(const float4*)&att1[lane * 4];
    const float4 bb = *(const float4*)&b1[lane * 4];
    int beg = g_rowptr[d], end = g_rowptr[d + 1];

    float m = -INFINITY, s = 0.f;
    float ax = 0.f, ay = 0.f, az = 0.f, aw = 0.f;

    float4 xl0, xl1;
    xl0 = *(const float4*)&xlbase[(size_t)g_csr[beg] * 128 + lane * 4];
    if (beg + 1 < end)
        xl1 = *(const float4*)&xlbase[(size_t)g_csr[beg + 1] * 128 + lane * 4];
    for (int j = beg; j < end; j++) {
        float4 xl2;
        if (j + 2 < end)
            xl2 = *(const float4*)&xlbase[(size_t)g_csr[j + 2] * 128 + lane * 4];
        float ex = lrelu(xl0.x + xr.x);
        float ey = lrelu(xl0.y + xr.y);
        float ez = lrelu(xl0.z + xr.z);
        float ew = lrelu(xl0.w + xr.w);
        float p = ex * av.x + ey * av.y + ez * av.z + ew * av.w;
        p += __shfl_xor_sync(0xffffffffu, p, 1);
        p += __shfl_xor_sync(0xffffffffu, p, 2);
        float mn = fmaxf(m, p);
        float f  = __expf(m - mn);
        float wt = __expf(p - mn);
        s  = s * f + wt;
        ax = ax * f + xl0.x * wt;
        ay = ay * f + xl0.y * wt;
        az = az * f + xl0.z * wt;
        aw = aw * f + xl0.w * wt;
        m = mn;
        xl0 = xl1; xl1 = xl2;
    }
    float inv = 1.f / s;
    float4 o;
    o.x = elu1(ax * inv + bb.x);
    o.y = elu1(ay * inv + bb.y);
    o.z = elu1(az * inv + bb.z);
    o.w = elu1(aw * inv + bb.w);
    *(float4*)&g_h1[(size_t)d * 128 + lane * 4] = o;
}

// ---------------- conv2 transforms -----------------------------------------
__global__ void conv2_transform(const float* __restrict__ h,
                                const float* __restrict__ Wl2,
                                const float* __restrict__ Wr2) {
    __shared__ float sw[128 * 32];
    __shared__ float sh[8][128];
    int t = threadIdx.x;
    for (int i = t; i < 128 * 16; i += 256) {
        int k = i >> 4, c = i & 15;
        sw[k * 32 + c]      = Wl2[i];
        sw[k * 32 + 16 + c] = Wr2[i];
    }
    int row0 = blockIdx.x * 8;
    for (int i = t; i < 8 * 128; i += 256) {
        int r = i >> 7;
        sh[r][i & 127] = h[(size_t)(row0 + r) * 128 + (i & 127)];
    }
    __syncthreads();
    int warp = t >> 5, lane = t & 31;
    int row = row0 + warp;
    float acc = 0.f;
#pragma unroll
    for (int k = 0; k < 128; k++) acc += sh[warp][k] * sw[k * 32 + lane];
    g_hlr[(size_t)row * 32 + lane] = acc;
}

// ---------------- conv2 aggregation + log_softmax ---------------------------
__global__ void conv2_agg(const float* __restrict__ att2, const float* __restrict__ b2,
                          float* __restrict__ out) {
    int tid = blockIdx.x * blockDim.x + threadIdx.x;
    int d = tid >> 4;
    int l = tid & 15;
    unsigned hm = 0xFFFFu << (((threadIdx.x & 31) >> 4) * 16);

    float xr = g_hlr[(size_t)d * 32 + 16 + l];
    float a  = att2[l];
    int beg = g_rowptr[d], end = g_rowptr[d + 1];

    float m = -INFINITY, s = 0.f, acc = 0.f;
    int src = g_csr[beg];
    float xl = g_hlr[(size_t)src * 32 + l];
    for (int j = beg; j < end; j++) {
        float xln = 0.f;
        if (j + 1 < end) {
            int nsrc = g_csr[j + 1];
            xln = g_hlr[(size_t)nsrc * 32 + l];
        }
        float p = lrelu(xl + xr) * a;
        p += __shfl_xor_sync(hm, p, 1);
        p += __shfl_xor_sync(hm, p, 2);
        p += __shfl_xor_sync(hm, p, 4);
        p += __shfl_xor_sync(hm, p, 8);
        float mn = fmaxf(m, p);
        float f  = __expf(m - mn);
        float w  = __expf(p - mn);
        s   = s * f + w;
        acc = acc * f + xl * w;
        m = mn;
        xl = xln;
    }
    float v = acc / s + b2[l];
    float mm = v;
#pragma unroll
    for (int k = 8; k >= 1; k >>= 1) mm = fmaxf(mm, __shfl_xor_sync(hm, mm, k));
    float pe = expf(v - mm);
    float ss = pe;
#pragma unroll
    for (int k = 8; k >= 1; k >>= 1) ss += __shfl_xor_sync(hm, ss, k);
    out[(size_t)d * 16 + l] = v - mm - logf(ss);
}

// ---------------- side stream (created at static init) ---------------------
static cudaStream_t s_csr = 0;
static cudaEvent_t  ev_fork = 0, ev_join = 0;
namespace {
struct StreamInit {
    StreamInit() {
        cudaStreamCreateWithFlags(&s_csr, cudaStreamNonBlocking);
        cudaEventCreateWithFlags(&ev_fork, cudaEventDisableTiming);
        cudaEventCreateWithFlags(&ev_join, cudaEventDisableTiming);
    }
} s_init;
}

// ---------------- launch ----------------
extern "C" void kernel_launch(void* const* d_in, const int* in_sizes, int n_in,
                              void* d_out, int out_size) {
    const float* x    = (const float*)d_in[0];
    const void*  ei   = d_in[1];
    const float* Wl1  = (const float*)d_in[2];
    const float* Wr1  = (const float*)d_in[3];
    const float* att1 = (const float*)d_in[4];
    const float* b1   = (const float*)d_in[5];
    const float* Wk   = (const float*)d_in[6];
    const float* bk   = (const float*)d_in[7];
    const float* Wl2  = (const float*)d_in[8];
    const float* Wr2  = (const float*)d_in[9];
    const float* att2 = (const float*)d_in[10];
    const float* b2   = (const float*)d_in[11];
    float* out = (float*)d_out;

    cudaFuncSetAttribute(mma_gemm, cudaFuncAttributeMaxDynamicSharedMemorySize, SMEM_MMA_SZ);

    float *xlxr, *h1, *h2;
    cudaGetSymbolAddress((void**)&xlxr, g_xlxr);
    cudaGetSymbolAddress((void**)&h1, g_h1);
    cudaGetSymbolAddress((void**)&h2, g_h2);
    float* xl = xlxr;
    float* xr = xlxr + (size_t)NN * 128;

    // 1: weight hi/lo images (5 matrices)
    wconv<<<5, 128>>>(Wl1, Wr1, Wk, Wk + 128 * 128, Wk + 2 * 128 * 128);
    // 2: deg=0 + dtype detect
    init_detect<<<NB, 256>>>(ei);

    // ---- fork: CSR build on side stream, conv1 GEMM on main stream ----
    cudaEventRecord(ev_fork, 0);
    cudaStreamWaitEvent(s_csr, ev_fork, 0);

    // 3: degrees (side stream)
    degree_k <<<(EE + 255) / 256, 256, 0, s_csr>>>(ei);
    // 4: conv1 xl+xr transforms (PROFILED SLOT — tensor cores, overlaps CSR)
    mma_gemm<<<dim3(GX128, 2), 256, SMEM_MMA_SZ>>>(x, 0, 1, xl, xr, nullptr, 0);
    // 5-8: rest of CSR build (side stream)
    scan_part<<<NB, 256, 0, s_csr>>>();
    scan_mid <<<1, 256, 0, s_csr>>>();
    scan_add <<<NB, 256, 0, s_csr>>>();
    scatter_k<<<(EE + 255) / 256, 256, 0, s_csr>>>(ei);
    cudaEventRecord(ev_join, s_csr);

    // ---- join ----
    cudaStreamWaitEvent(0, ev_join, 0);

    // conv1 aggregation (+elu) -> g_h1
    conv1_agg<<<NN / 8, 256>>>(att1, b1);

    // knowledge layers (tensor cores, bias + elu fused)
    mma_gemm<<<dim3(GX128, 1), 256, SMEM_MMA_SZ>>>(h1, 2, 2, h2, h2, bk,       1);
    mma_gemm<<<dim3(GX128, 1), 256, SMEM_MMA_SZ>>>(h2, 3, 3, h1, h1, bk + 128, 1);
    mma_gemm<<<dim3(GX128, 1), 256, SMEM_MMA_SZ>>>(h1, 4, 4, h2, h2, bk + 256, 1);

    // conv2 transforms -> g_hlr
    conv2_transform<<<NN / 8, 256>>>(h2, Wl2, Wr2);

    // conv2 aggregation + log_softmax -> out
    conv2_agg<<<NN / 16, 256>>>(att2, b2, out);
}

// round 12
// speedup vs baseline: 1.3288x; 1.0056x over previous
#include <cuda_runtime.h>
#include <cuda_bf16.h>
#include <math.h>
#include <stdint.h>

#define NN 50000
#define EE 800000
#define ET 850000   // EE + NN self loops
#define NB 196      // ceil(NN/256)
#define GX128 391   // ceil(NN/128)
#define GPAD 136    // padded row: 136 bf16 = 272B (conflict-free ldmatrix)
#define SMEM_MMA_SZ (2 * 128 * GPAD * 2)   // 69632 B: B hi + lo images

// ---------------- scratch (static device allocations only) ----------------
__device__ float g_xlxr[(size_t)NN * 256];   // [0:N*128)=xl dense, [N*128:)=xr dense
__device__ float g_h1[(size_t)NN * 128];
__device__ float g_h2[(size_t)NN * 128];
__device__ float g_hlr[(size_t)NN * 32];
__device__ int   g_deg[NN];
__device__ int   g_rowptr[NN + 1];
__device__ int   g_cursor[NN];
__device__ int   g_csr[ET];
__device__ int   g_part[256];
__device__ int   g_is64;
// weight images: [matrix 0..4][hi/lo] as [k][n] rows padded to 272B
__device__ __align__(16) __nv_bfloat16 g_wimg[5][2][128 * GPAD];

__device__ __forceinline__ float lrelu(float x) { return x > 0.f ? x : 0.2f * x; }
__device__ __forceinline__ float elu1 (float x) { return x > 0.f ? x : expm1f(x); }

__device__ __forceinline__ uint32_t smem_u32(const void* p) {
    uint32_t a;
    asm("{ .reg .u64 t; cvta.to.shared.u64 t, %1; cvt.u32.u64 %0, t; }"
        : "=r"(a) : "l"(p));
    return a;
}
__device__ __forceinline__ uint32_t pk2(__nv_bfloat16 a, __nv_bfloat16 b) {
    return (uint32_t)__bfloat16_as_ushort(a) | ((uint32_t)__bfloat16_as_ushort(b) << 16);
}
// split float2 into bf16x2 hi + bf16x2 lo (residual)
__device__ __forceinline__ void split2(float2 f, uint32_t& h, uint32_t& l) {
    __nv_bfloat16 hx = __float2bfloat16_rn(f.x);
    __nv_bfloat16 hy = __float2bfloat16_rn(f.y);
    float rx = f.x - __bfloat162float(hx);
    float ry = f.y - __bfloat162float(hy);
    h = pk2(hx, hy);
    l = pk2(__float2bfloat16_rn(rx), __float2bfloat16_rn(ry));
}

__device__ __forceinline__ void ldsm_x4t(uint32_t& r0, uint32_t& r1,
                                         uint32_t& r2, uint32_t& r3, uint32_t addr) {
    asm volatile("ldmatrix.sync.aligned.m8n8.x4.trans.shared.b16 {%0,%1,%2,%3}, [%4];"
        : "=r"(r0), "=r"(r1), "=r"(r2), "=r"(r3) : "r"(addr));
}
__device__ __forceinline__ void mma16816(float* d, const uint32_t* a,
                                         uint32_t b0, uint32_t b1) {
    asm volatile(
        "mma.sync.aligned.m16n8k16.row.col.f32.bf16.bf16.f32 "
        "{%0,%1,%2,%3}, {%4,%5,%6,%7}, {%8,%9}, {%0,%1,%2,%3};"
        : "+f"(d[0]), "+f"(d[1]), "+f"(d[2]), "+f"(d[3])
        : "r"(a[0]), "r"(a[1]), "r"(a[2]), "r"(a[3]), "r"(b0), "r"(b1));
}

// ---------------- weight split kernel: W[k][n] -> hi/lo images --------------
// grid (128, 5), block 128: element (k=blockIdx.x, n=tid) of matrix blockIdx.y
__global__ void wconv(const float* __restrict__ w0, const float* __restrict__ w1,
                      const float* __restrict__ w2, const float* __restrict__ w3,
                      const float* __restrict__ w4) {
    int b = blockIdx.y;
    const float* W = (b == 0) ? w0 : (b == 1) ? w1 : (b == 2) ? w2 : (b == 3) ? w3 : w4;
    int k = blockIdx.x, n = threadIdx.x;
    float v = W[(size_t)k * 128 + n];
    __nv_bfloat16 h = __float2bfloat16_rn(v);
    __nv_bfloat16 l = __float2bfloat16_rn(v - __bfloat162float(h));
    g_wimg[b][0][k * GPAD + n] = h;
    g_wimg[b][1][k * GPAD + n] = l;
}

// ---------------- tensor-core GEMM: C[NN,128] = A[NN,128] @ W --------------
// bf16 hi/lo split, 3 mma passes, fp32 accum. 128(M)x128(N) per 256-thread
// CTA, processed as two sequential 64-col halves so acc is only 32 regs.
// grid=(391, nmat). mat=blockIdx.y selects (img, C).
__global__ void __launch_bounds__(256) mma_gemm(
    const float* __restrict__ A, int i0, int i1,
    float* __restrict__ C0, float* __restrict__ C1,
    const float* __restrict__ bias, int act) {
    extern __shared__ __align__(16) __nv_bfloat16 sB[];   // hi[128*GPAD] | lo[128*GPAD]
    const int t = threadIdx.x, lane = t & 31, wid = t >> 5;
    const int mat = blockIdx.y;
    const int img = mat ? i1 : i0;
    float* C = mat ? C1 : C0;
    const int m0 = blockIdx.x * 128 + wid * 16;

    // stage B hi+lo images: one contiguous 69632B copy (4352 uint4)
    {
        const uint4* src = (const uint4*)&g_wimg[img][0][0];
        uint4* dst = (uint4*)sB;
#pragma unroll
        for (int i = 0; i < 17; i++) dst[t + i * 256] = src[t + i * 256];
    }
    __syncthreads();

    const int g  = lane >> 2;        // fragment row group 0..7
    const int cp = (lane & 3) * 2;   // fragment col pair
    const float* Ar0 = A + (size_t)(m0 + g) * 128;
    const float* Ar8 = A + (size_t)(m0 + g + 8) * 128;
    const bool v0 = (m0 + g) < NN;
    const bool v8 = (m0 + g + 8) < NN;

    // ldmatrix per-thread address pieces
    const int bi   = lane >> 3;
    const int brow = (lane & 7) + (bi & 1) * 8;
    const int bcol = (bi >> 1) * 8;
    const uint32_t sbH = smem_u32(sB);
    const uint32_t sbL = sbH + 128 * GPAD * 2;

    const int r0w = m0 + g, r8w = m0 + g + 8;

#pragma unroll
    for (int nh = 0; nh < 2; nh++) {
        const uint32_t hoff = (uint32_t)nh * 128;   // 64 cols * 2 B
        float acc[8][4];
#pragma unroll
        for (int i = 0; i < 8; i++)
#pragma unroll
            for (int j = 0; j < 4; j++) acc[i][j] = 0.f;

        for (int ks = 0; ks < 8; ks++) {
            const int k0 = ks * 16;
            // A fragment from global (L2-hot on 2nd half), split hi/lo
            float2 f0 = v0 ? *(const float2*)(Ar0 + k0 + cp)     : make_float2(0.f, 0.f);
            float2 f1 = v8 ? *(const float2*)(Ar8 + k0 + cp)     : make_float2(0.f, 0.f);
            float2 f2 = v0 ? *(const float2*)(Ar0 + k0 + cp + 8) : make_float2(0.f, 0.f);
            float2 f3 = v8 ? *(const float2*)(Ar8 + k0 + cp + 8) : make_float2(0.f, 0.f);
            uint32_t ah[4], al[4];
            split2(f0, ah[0], al[0]);
            split2(f1, ah[1], al[1]);
            split2(f2, ah[2], al[2]);
            split2(f3, ah[3], al[3]);

            const uint32_t rowoff = (uint32_t)((k0 + brow) * GPAD + bcol) * 2 + hoff;
#pragma unroll
            for (int ng = 0; ng < 4; ng++) {
                uint32_t bh0, bh1, bh2, bh3, bl0, bl1, bl2, bl3;
                ldsm_x4t(bh0, bh1, bh2, bh3, sbH + rowoff + ng * 32);
                ldsm_x4t(bl0, bl1, bl2, bl3, sbL + rowoff + ng * 32);
                mma16816(acc[2 * ng],     ah, bh0, bh1);
                mma16816(acc[2 * ng + 1], ah, bh2, bh3);
                mma16816(acc[2 * ng],     ah, bl0, bl1);
                mma16816(acc[2 * ng + 1], ah, bl2, bl3);
                mma16816(acc[2 * ng],     al, bh0, bh1);
                mma16816(acc[2 * ng + 1], al, bh2, bh3);
            }
        }

        // epilogue for this 64-col half
#pragma unroll
        for (int nt = 0; nt < 8; nt++) {
            int gc = nh * 64 + nt * 8 + cp;
            float v00 = acc[nt][0], v01 = acc[nt][1];
            float v10 = acc[nt][2], v11 = acc[nt][3];
            if (bias) {
                float b0v = bias[gc], b1v = bias[gc + 1];
                v00 += b0v; v01 += b1v; v10 += b0v; v11 += b1v;
            }
            if (act == 1) { v00 = elu1(v00); v01 = elu1(v01); v10 = elu1(v10); v11 = elu1(v11); }
            if (v0) *(float2*)&C[(size_t)r0w * 128 + gc] = make_float2(v00, v01);
            if (v8) *(float2*)&C[(size_t)r8w * 128 + gc] = make_float2(v10, v11);
        }
    }
}

// ---------------- init deg=0 + dtype detect (block 0) ----------------------
__global__ void init_detect(const void* ei) {
    int i = blockIdx.x * blockDim.x + threadIdx.x;
    if (i < NN) g_deg[i] = 0;
    if (blockIdx.x == 0) {
        __shared__ int cnt;
        if (threadIdx.x == 0) cnt = 0;
        __syncthreads();
        const unsigned* p = (const unsigned*)ei;
        int nz = 0;
        for (int k = threadIdx.x; k < 2048; k += 256)
            if (p[2 * k + 1] != 0u) nz++;
        if (nz) atomicAdd(&cnt, nz);
        __syncthreads();
        if (threadIdx.x == 0) g_is64 = (cnt < 8) ? 1 : 0;
    }
}

__device__ __forceinline__ int edge_val(const void* ei, int idx, int is64) {
    if (is64) return (int)((const long long*)ei)[idx];
    return ((const int*)ei)[idx];
}

__global__ void degree_k(const void* ei) {
    int i = blockIdx.x * blockDim.x + threadIdx.x;
    if (i >= EE) return;
    int is64 = g_is64;
    int dst = edge_val(ei, EE + i, is64);
    atomicAdd(&g_deg[dst], 1);
}

// ---------------- parallel scan over (deg[i]+1) ----------------------------
__global__ void scan_part() {
    int t = threadIdx.x, lane = t & 31, w = t >> 5;
    int i = blockIdx.x * 256 + t;
    int v = (i < NN) ? g_deg[i] + 1 : 0;
#pragma unroll
    for (int off = 16; off >= 1; off >>= 1) v += __shfl_xor_sync(0xffffffffu, v, off);
    __shared__ int ws[8];
    if (lane == 0) ws[w] = v;
    __syncthreads();
    if (t == 0) {
        int s = 0;
#pragma unroll
        for (int k = 0; k < 8; k++) s += ws[k];
        g_part[blockIdx.x] = s;
    }
}

__global__ void scan_mid() {
    int t = threadIdx.x, lane = t & 31, w = t >> 5;
    int d = (t < NB) ? g_part[t] : 0;
    int v = d;
#pragma unroll
    for (int off = 1; off < 32; off <<= 1) {
        int u = __shfl_up_sync(0xffffffffu, v, off);
        if (lane >= off) v += u;
    }
    __shared__ int ws[8];
    if (lane == 31) ws[w] = v;
    __syncthreads();
    if (w == 0 && lane < 8) {
        int s = ws[lane];
#pragma unroll
        for (int off = 1; off < 8; off <<= 1) {
            int u = __shfl_up_sync(0xffu, s, off);
            if (lane >= off) s += u;
        }
        ws[lane] = s;
    }
    __syncthreads();
    int incl = v + (w > 0 ? ws[w - 1] : 0);
    if (t < NB) g_part[t] = incl - d;
    if (t == 255) g_rowptr[NN] = incl;
}

__global__ void scan_add() {
    int t = threadIdx.x, lane = t & 31, w = t >> 5;
    int i = blockIdx.x * 256 + t;
    int d = (i < NN) ? g_deg[i] + 1 : 0;
    int v = d;
#pragma unroll
    for (int off = 1; off < 32; off <<= 1) {
        int u = __shfl_up_sync(0xffffffffu, v, off);
        if (lane >= off) v += u;
    }
    __shared__ int ws[8];
    if (lane == 31) ws[w] = v;
    __syncthreads();
    if (w == 0 && lane < 8) {
        int s = ws[lane];
#pragma unroll
        for (int off = 1; off < 8; off <<= 1) {
            int u = __shfl_up_sync(0xffu, s, off);
            if (lane >= off) s += u;
        }
        ws[lane] = s;
    }
    __syncthreads();
    int excl = g_part[blockIdx.x] + v - d + (w > 0 ? ws[w - 1] : 0);
    if (i < NN) {
        g_rowptr[i] = excl;
        g_csr[excl] = i;
        g_cursor[i] = excl + 1;
    }
}

__global__ void scatter_k(const void* ei) {
    int i = blockIdx.x * blockDim.x + threadIdx.x;
    if (i >= EE) return;
    int is64 = g_is64;
    int s = edge_val(ei, i, is64);
    int d = edge_val(ei, EE + i, is64);
    int pos = atomicAdd(&g_cursor[d], 1);
    g_csr[pos] = s;
}

// ---------------- conv1 aggregation: warp per node, 8-head online softmax --
// 4-deep row pipeline + 8-deep index pipeline, branch-free clamped prefetch.
__global__ void conv1_agg(const float* __restrict__ att1, const float* __restrict__ b1) {
    int gw   = (blockIdx.x * blockDim.x + threadIdx.x) >> 5;
    int lane = threadIdx.x & 31;
    int d = gw;
    const float* xlbase = g_xlxr;
    const float* xrbase = g_xlxr + (size_t)NN * 128;
    const float4 xr = *(const float4*)&xrbase[(size_t)d * 128 + lane * 4];
    const float4 av = *(const float4*)&att1[lane * 4];
    const float4 bb = *(const float4*)&b1[lane * 4];
    const int beg = g_rowptr[d], end = g_rowptr[d + 1];
    const int last = end - 1;

    float m = -INFINITY, s = 0.f;
    float ax = 0.f, ay = 0.f, az = 0.f, aw = 0.f;

    // index pipeline (8 ahead) and row pipeline (4 deep), clamped
    int i4[4];
    float4 r[4];
#pragma unroll
    for (int k = 0; k < 4; k++) {
        int j0 = min(beg + k, last);
        int j4 = min(beg + 4 + k, last);
        int src = g_csr[j0];
        i4[k] = g_csr[j4];
        r[k] = *(const float4*)&xlbase[(size_t)src * 128 + lane * 4];
    }

    for (int j = beg; j < end; j++) {
        int inew = g_csr[min(j + 8, last)];
        float4 rnew = *(const float4*)&xlbase[(size_t)i4[0] * 128 + lane * 4];

        float4 xl = r[0];
        float ex = lrelu(xl.x + xr.x);
        float ey = lrelu(xl.y + xr.y);
        float ez = lrelu(xl.z + xr.z);
        float ew = lrelu(xl.w + xr.w);
        float p = ex * av.x + ey * av.y + ez * av.z + ew * av.w;
        p += __shfl_xor_sync(0xffffffffu, p, 1);
        p += __shfl_xor_sync(0xffffffffu, p, 2);
        float mn = fmaxf(m, p);
        float f  = __expf(m - mn);
        float wt = __expf(p - mn);
        s  = s * f + wt;
        ax = ax * f + xl.x * wt;
        ay = ay * f + xl.y * wt;
        az = az * f + xl.z * wt;
        aw = aw * f + xl.w * wt;
        m = mn;

        r[0] = r[1]; r[1] = r[2]; r[2] = r[3]; r[3] = rnew;
        i4[0] = i4[1]; i4[1] = i4[2]; i4[2] = i4[3]; i4[3] = inew;
    }
    float inv = 1.f / s;
    float4 o;
    o.x = elu1(ax * inv + bb.x);
    o.y = elu1(ay * inv + bb.y);
    o.z = elu1(az * inv + bb.z);
    o.w = elu1(aw * inv + bb.w);
    *(float4*)&g_h1[(size_t)d * 128 + lane * 4] = o;
}

// ---------------- conv2 transforms -----------------------------------------
__global__ void conv2_transform(const float* __restrict__ h,
                                const float* __restrict__ Wl2,
                                const float* __restrict__ Wr2) {
    __shared__ float sw[128 * 32];
    __shared__ float sh[8][128];
    int t = threadIdx.x;
    for (int i = t; i < 128 * 16; i += 256) {
        int k = i >> 4, c = i & 15;
        sw[k * 32 + c]      = Wl2[i];
        sw[k * 32 + 16 + c] = Wr2[i];
    }
    int row0 = blockIdx.x * 8;
    for (int i = t; i < 8 * 128; i += 256) {
        int r = i >> 7;
        sh[r][i & 127] = h[(size_t)(row0 + r) * 128 + (i & 127)];
    }
    __syncthreads();
    int warp = t >> 5, lane = t & 31;
    int row = row0 + warp;
    float acc = 0.f;
#pragma unroll
    for (int k = 0; k < 128; k++) acc += sh[warp][k] * sw[k * 32 + lane];
    g_hlr[(size_t)row * 32 + lane] = acc;
}

// ---------------- conv2 aggregation + log_softmax ---------------------------
// 4-deep row pipeline + 8-deep index pipeline, branch-free clamped prefetch.
__global__ void conv2_agg(const float* __restrict__ att2, const float* __restrict__ b2,
                          float* __restrict__ out) {
    int tid = blockIdx.x * blockDim.x + threadIdx.x;
    int d = tid >> 4;
    int l = tid & 15;
    unsigned hm = 0xFFFFu << (((threadIdx.x & 31) >> 4) * 16);

    float xr = g_hlr[(size_t)d * 32 + 16 + l];
    float a  = att2[l];
    const int beg = g_rowptr[d], end = g_rowptr[d + 1];
    const int last = end - 1;

    float m = -INFINITY, s = 0.f, acc = 0.f;

    int i4[4];
    float r[4];
#pragma unroll
    for (int k = 0; k < 4; k++) {
        int j0 = min(beg + k, last);
        int j4 = min(beg + 4 + k, last);
        int src = g_csr[j0];
        i4[k] = g_csr[j4];
        r[k] = g_hlr[(size_t)src * 32 + l];
    }

    for (int j = beg; j < end; j++) {
        int inew = g_csr[min(j + 8, last)];
        float rnew = g_hlr[(size_t)i4[0] * 32 + l];

        float xl = r[0];
        float p = lrelu(xl + xr) * a;
        p += __shfl_xor_sync(hm, p, 1);
        p += __shfl_xor_sync(hm, p, 2);
        p += __shfl_xor_sync(hm, p, 4);
        p += __shfl_xor_sync(hm, p, 8);
        float mn = fmaxf(m, p);
        float f  = __expf(m - mn);
        float w  = __expf(p - mn);
        s   = s * f + w;
        acc = acc * f + xl * w;
        m = mn;

        r[0] = r[1]; r[1] = r[2]; r[2] = r[3]; r[3] = rnew;
        i4[0] = i4[1]; i4[1] = i4[2]; i4[2] = i4[3]; i4[3] = inew;
    }
    float v = acc / s + b2[l];
    float mm = v;
#pragma unroll
    for (int k = 8; k >= 1; k >>= 1) mm = fmaxf(mm, __shfl_xor_sync(hm, mm, k));
    float pe = expf(v - mm);
    float ss = pe;
#pragma unroll
    for (int k = 8; k >= 1; k >>= 1) ss += __shfl_xor_sync(hm, ss, k);
    out[(size_t)d * 16 + l] = v - mm - logf(ss);
}

// ---------------- side stream (created at static init) ---------------------
static cudaStream_t s_csr = 0;
static cudaEvent_t  ev_fork = 0, ev_join = 0;
namespace {
struct StreamInit {
    StreamInit() {
        cudaStreamCreateWithFlags(&s_csr, cudaStreamNonBlocking);
        cudaEventCreateWithFlags(&ev_fork, cudaEventDisableTiming);
        cudaEventCreateWithFlags(&ev_join, cudaEventDisableTiming);
    }
} s_init;
}

// ---------------- launch ----------------
extern "C" void kernel_launch(void* const* d_in, const int* in_sizes, int n_in,
                              void* d_out, int out_size) {
    const float* x    = (const float*)d_in[0];
    const void*  ei   = d_in[1];
    const float* Wl1  = (const float*)d_in[2];
    const float* Wr1  = (const float*)d_in[3];
    const float* att1 = (const float*)d_in[4];
    const float* b1   = (const float*)d_in[5];
    const float* Wk   = (const float*)d_in[6];
    const float* bk   = (const float*)d_in[7];
    const float* Wl2  = (const float*)d_in[8];
    const float* Wr2  = (const float*)d_in[9];
    const float* att2 = (const float*)d_in[10];
    const float* b2   = (const float*)d_in[11];
    float* out = (float*)d_out;

    cudaFuncSetAttribute(mma_gemm, cudaFuncAttributeMaxDynamicSharedMemorySize, SMEM_MMA_SZ);

    float *xlxr, *h1, *h2;
    cudaGetSymbolAddress((void**)&xlxr, g_xlxr);
    cudaGetSymbolAddress((void**)&h1, g_h1);
    cudaGetSymbolAddress((void**)&h2, g_h2);
    float* xl = xlxr;
    float* xr = xlxr + (size_t)NN * 128;

    // 1: weight hi/lo images (parallelized: 1 element/thread)
    wconv<<<dim3(128, 5), 128>>>(Wl1, Wr1, Wk, Wk + 128 * 128, Wk + 2 * 128 * 128);
    // 2: deg=0 + dtype detect
    init_detect<<<NB, 256>>>(ei);

    // ---- fork: CSR build on side stream, conv1 GEMM on main stream ----
    cudaEventRecord(ev_fork, 0);
    cudaStreamWaitEvent(s_csr, ev_fork, 0);

    // 3: degrees (side stream)
    degree_k <<<(EE + 255) / 256, 256, 0, s_csr>>>(ei);
    // 4: conv1 xl+xr transforms (PROFILED SLOT — tensor cores, overlaps CSR)
    mma_gemm<<<dim3(GX128, 2), 256, SMEM_MMA_SZ>>>(x, 0, 1, xl, xr, nullptr, 0);
    // 5-8: rest of CSR build (side stream)
    scan_part<<<NB, 256, 0, s_csr>>>();
    scan_mid <<<1, 256, 0, s_csr>>>();
    scan_add <<<NB, 256, 0, s_csr>>>();
    scatter_k<<<(EE + 255) / 256, 256, 0, s_csr>>>(ei);
    cudaEventRecord(ev_join, s_csr);

    // ---- join ----
    cudaStreamWaitEvent(0, ev_join, 0);

    // conv1 aggregation (+elu) -> g_h1
    conv1_agg<<<NN / 8, 256>>>(att1, b1);

    // knowledge layers (tensor cores, bias + elu fused)
    mma_gemm<<<dim3(GX128, 1), 256, SMEM_MMA_SZ>>>(h1, 2, 2, h2, h2, bk,       1);
    mma_gemm<<<dim3(GX128, 1), 256, SMEM_MMA_SZ>>>(h2, 3, 3, h1, h1, bk + 128, 1);
    mma_gemm<<<dim3(GX128, 1), 256, SMEM_MMA_SZ>>>(h1, 4, 4, h2, h2, bk + 256, 1);

    // conv2 transforms -> g_hlr
    conv2_transform<<<NN / 8, 256>>>(h2, Wl2, Wr2);

    // conv2 aggregation + log_softmax -> out
    conv2_agg<<<NN / 16, 256>>>(att2, b2, out);
}

// round 13
// speedup vs baseline: 1.4405x; 1.0841x over previous
#include <cuda_runtime.h>
#include <cuda_fp16.h>
#include <math.h>
#include <stdint.h>

#define NN 50000
#define EE 800000
#define ET 850000   // EE + NN self loops
#define NB 196      // ceil(NN/256)
#define GX128 391   // ceil(NN/128)
#define GPAD 136    // padded row: 136 fp16 = 272B (conflict-free ldmatrix)
#define SMEM_MMA_SZ (128 * GPAD * 2)   // 34816 B: single fp16 B image

// ---------------- scratch (static device allocations only) ----------------
__device__ float g_xlxr[(size_t)NN * 256];   // [0:N*128)=xl dense, [N*128:)=xr dense
__device__ float g_h1[(size_t)NN * 128];
__device__ float g_h2[(size_t)NN * 128];
__device__ float g_hlr[(size_t)NN * 32];
__device__ int   g_deg[NN];
__device__ int   g_rowptr[NN + 1];
__device__ int   g_cursor[NN];
__device__ int   g_csr[ET];
__device__ int   g_part[256];
__device__ int   g_is64;
// weight images: [matrix 0..4] as fp16 [k][n] rows padded to 272B
__device__ __align__(16) __half g_wimg[5][128 * GPAD];

__device__ __forceinline__ float lrelu(float x) { return x > 0.f ? x : 0.2f * x; }
__device__ __forceinline__ float elu1 (float x) { return x > 0.f ? x : expm1f(x); }

__device__ __forceinline__ uint32_t smem_u32(const void* p) {
    uint32_t a;
    asm("{ .reg .u64 t; cvta.to.shared.u64 t, %1; cvt.u32.u64 %0, t; }"
        : "=r"(a) : "l"(p));
    return a;
}
// pack float2 -> fp16x2
__device__ __forceinline__ uint32_t pkh(float2 f) {
    __half2 h = __float22half2_rn(f);
    return *(uint32_t*)&h;
}

__device__ __forceinline__ void ldsm_x4t(uint32_t& r0, uint32_t& r1,
                                         uint32_t& r2, uint32_t& r3, uint32_t addr) {
    asm volatile("ldmatrix.sync.aligned.m8n8.x4.trans.shared.b16 {%0,%1,%2,%3}, [%4];"
        : "=r"(r0), "=r"(r1), "=r"(r2), "=r"(r3) : "r"(addr));
}
__device__ __forceinline__ void mma16816(float* d, const uint32_t* a,
                                         uint32_t b0, uint32_t b1) {
    asm volatile(
        "mma.sync.aligned.m16n8k16.row.col.f32.f16.f16.f32 "
        "{%0,%1,%2,%3}, {%4,%5,%6,%7}, {%8,%9}, {%0,%1,%2,%3};"
        : "+f"(d[0]), "+f"(d[1]), "+f"(d[2]), "+f"(d[3])
        : "r"(a[0]), "r"(a[1]), "r"(a[2]), "r"(a[3]), "r"(b0), "r"(b1));
}

// ---------------- weight convert kernel: W[k][n] -> fp16 image --------------
// grid (128, 5), block 128: element (k=blockIdx.x, n=tid) of matrix blockIdx.y
__global__ void wconv(const float* __restrict__ w0, const float* __restrict__ w1,
                      const float* __restrict__ w2, const float* __restrict__ w3,
                      const float* __restrict__ w4) {
    int b = blockIdx.y;
    const float* W = (b == 0) ? w0 : (b == 1) ? w1 : (b == 2) ? w2 : (b == 3) ? w3 : w4;
    int k = blockIdx.x, n = threadIdx.x;
    g_wimg[b][k * GPAD + n] = __float2half_rn(W[(size_t)k * 128 + n]);
}

// ---------------- tensor-core GEMM: C[NN,128] = A[NN,128] @ W --------------
// fp16 single-pass, fp32 accum. 128(M)x128(N) per 256-thread CTA, processed
// as two sequential 64-col halves (acc = 32 regs). grid=(391, nmat).
__global__ void __launch_bounds__(256) mma_gemm(
    const float* __restrict__ A, int i0, int i1,
    float* __restrict__ C0, float* __restrict__ C1,
    const float* __restrict__ bias, int act) {
    extern __shared__ __align__(16) __half sB[];   // fp16 image [128*GPAD]
    const int t = threadIdx.x, lane = t & 31, wid = t >> 5;
    const int mat = blockIdx.y;
    const int img = mat ? i1 : i0;
    float* C = mat ? C1 : C0;
    const int m0 = blockIdx.x * 128 + wid * 16;

    // stage B image: 34816 B = 2176 uint4
    {
        const uint4* src = (const uint4*)&g_wimg[img][0];
        uint4* dst = (uint4*)sB;
        for (int i = t; i < 2176; i += 256) dst[i] = src[i];
    }
    __syncthreads();

    const int g  = lane >> 2;        // fragment row group 0..7
    const int cp = (lane & 3) * 2;   // fragment col pair
    const float* Ar0 = A + (size_t)(m0 + g) * 128;
    const float* Ar8 = A + (size_t)(m0 + g + 8) * 128;
    const bool v0 = (m0 + g) < NN;
    const bool v8 = (m0 + g + 8) < NN;

    // ldmatrix per-thread address pieces
    const int bi   = lane >> 3;
    const int brow = (lane & 7) + (bi & 1) * 8;
    const int bcol = (bi >> 1) * 8;
    const uint32_t sbH = smem_u32(sB);

    const int r0w = m0 + g, r8w = m0 + g + 8;

#pragma unroll
    for (int nh = 0; nh < 2; nh++) {
        const uint32_t hoff = (uint32_t)nh * 128;   // 64 cols * 2 B
        float acc[8][4];
#pragma unroll
        for (int i = 0; i < 8; i++)
#pragma unroll
            for (int j = 0; j < 4; j++) acc[i][j] = 0.f;

        for (int ks = 0; ks < 8; ks++) {
            const int k0 = ks * 16;
            // A fragment from global (L2-hot on 2nd half), fp16 convert
            float2 f0 = v0 ? *(const float2*)(Ar0 + k0 + cp)     : make_float2(0.f, 0.f);
            float2 f1 = v8 ? *(const float2*)(Ar8 + k0 + cp)     : make_float2(0.f, 0.f);
            float2 f2 = v0 ? *(const float2*)(Ar0 + k0 + cp + 8) : make_float2(0.f, 0.f);
            float2 f3 = v8 ? *(const float2*)(Ar8 + k0 + cp + 8) : make_float2(0.f, 0.f);
            uint32_t ah[4];
            ah[0] = pkh(f0); ah[1] = pkh(f1); ah[2] = pkh(f2); ah[3] = pkh(f3);

            const uint32_t rowoff = (uint32_t)((k0 + brow) * GPAD + bcol) * 2 + hoff;
#pragma unroll
            for (int ng = 0; ng < 4; ng++) {
                uint32_t b0, b1, b2, b3;
                ldsm_x4t(b0, b1, b2, b3, sbH + rowoff + ng * 32);
                mma16816(acc[2 * ng],     ah, b0, b1);
                mma16816(acc[2 * ng + 1], ah, b2, b3);
            }
        }

        // epilogue for this 64-col half
#pragma unroll
        for (int nt = 0; nt < 8; nt++) {
            int gc = nh * 64 + nt * 8 + cp;
            float v00 = acc[nt][0], v01 = acc[nt][1];
            float v10 = acc[nt][2], v11 = acc[nt][3];
            if (bias) {
                float b0v = bias[gc], b1v = bias[gc + 1];
                v00 += b0v; v01 += b1v; v10 += b0v; v11 += b1v;
            }
            if (act == 1) { v00 = elu1(v00); v01 = elu1(v01); v10 = elu1(v10); v11 = elu1(v11); }
            if (v0) *(float2*)&C[(size_t)r0w * 128 + gc] = make_float2(v00, v01);
            if (v8) *(float2*)&C[(size_t)r8w * 128 + gc] = make_float2(v10, v11);
        }
    }
}

// ---------------- init deg=0 + dtype detect (block 0) ----------------------
__global__ void init_detect(const void* ei) {
    int i = blockIdx.x * blockDim.x + threadIdx.x;
    if (i < NN) g_deg[i] = 0;
    if (blockIdx.x == 0) {
        __shared__ int cnt;
        if (threadIdx.x == 0) cnt = 0;
        __syncthreads();
        const unsigned* p = (const unsigned*)ei;
        int nz = 0;
        for (int k = threadIdx.x; k < 2048; k += 256)
            if (p[2 * k + 1] != 0u) nz++;
        if (nz) atomicAdd(&cnt, nz);
        __syncthreads();
        if (threadIdx.x == 0) g_is64 = (cnt < 8) ? 1 : 0;
    }
}

__device__ __forceinline__ int edge_val(const void* ei, int idx, int is64) {
    if (is64) return (int)((const long long*)ei)[idx];
    return ((const int*)ei)[idx];
}

__global__ void degree_k(const void* ei) {
    int i = blockIdx.x * blockDim.x + threadIdx.x;
    if (i >= EE) return;
    int is64 = g_is64;
    int dst = edge_val(ei, EE + i, is64);
    atomicAdd(&g_deg[dst], 1);
}

// ---------------- parallel scan over (deg[i]+1) ----------------------------
__global__ void scan_part() {
    int t = threadIdx.x, lane = t & 31, w = t >> 5;
    int i = blockIdx.x * 256 + t;
    int v = (i < NN) ? g_deg[i] + 1 : 0;
#pragma unroll
    for (int off = 16; off >= 1; off >>= 1) v += __shfl_xor_sync(0xffffffffu, v, off);
    __shared__ int ws[8];
    if (lane == 0) ws[w] = v;
    __syncthreads();
    if (t == 0) {
        int s = 0;
#pragma unroll
        for (int k = 0; k < 8; k++) s += ws[k];
        g_part[blockIdx.x] = s;
    }
}

__global__ void scan_mid() {
    int t = threadIdx.x, lane = t & 31, w = t >> 5;
    int d = (t < NB) ? g_part[t] : 0;
    int v = d;
#pragma unroll
    for (int off = 1; off < 32; off <<= 1) {
        int u = __shfl_up_sync(0xffffffffu, v, off);
        if (lane >= off) v += u;
    }
    __shared__ int ws[8];
    if (lane == 31) ws[w] = v;
    __syncthreads();
    if (w == 0 && lane < 8) {
        int s = ws[lane];
#pragma unroll
        for (int off = 1; off < 8; off <<= 1) {
            int u = __shfl_up_sync(0xffu, s, off);
            if (lane >= off) s += u;
        }
        ws[lane] = s;
    }
    __syncthreads();
    int incl = v + (w > 0 ? ws[w - 1] : 0);
    if (t < NB) g_part[t] = incl - d;
    if (t == 255) g_rowptr[NN] = incl;
}

__global__ void scan_add() {
    int t = threadIdx.x, lane = t & 31, w = t >> 5;
    int i = blockIdx.x * 256 + t;
    int d = (i < NN) ? g_deg[i] + 1 : 0;
    int v = d;
#pragma unroll
    for (int off = 1; off < 32; off <<= 1) {
        int u = __shfl_up_sync(0xffffffffu, v, off);
        if (lane >= off) v += u;
    }
    __shared__ int ws[8];
    if (lane == 31) ws[w] = v;
    __syncthreads();
    if (w == 0 && lane < 8) {
        int s = ws[lane];
#pragma unroll
        for (int off = 1; off < 8; off <<= 1) {
            int u = __shfl_up_sync(0xffu, s, off);
            if (lane >= off) s += u;
        }
        ws[lane] = s;
    }
    __syncthreads();
    int excl = g_part[blockIdx.x] + v - d + (w > 0 ? ws[w - 1] : 0);
    if (i < NN) {
        g_rowptr[i] = excl;
        g_csr[excl] = i;
        g_cursor[i] = excl + 1;
    }
}

__global__ void scatter_k(const void* ei) {
    int i = blockIdx.x * blockDim.x + threadIdx.x;
    if (i >= EE) return;
    int is64 = g_is64;
    int s = edge_val(ei, i, is64);
    int d = edge_val(ei, EE + i, is64);
    int pos = atomicAdd(&g_cursor[d], 1);
    g_csr[pos] = s;
}

// ---------------- conv1 aggregation: warp per node, 8-head online softmax --
__global__ void conv1_agg(const float* __restrict__ att1, const float* __restrict__ b1) {
    int gw   = (blockIdx.x * blockDim.x + threadIdx.x) >> 5;
    int lane = threadIdx.x & 31;
    int d = gw;
    const float* xlbase = g_xlxr;
    const float* xrbase = g_xlxr + (size_t)NN * 128;
    const float4 xr = *(const float4*)&xrbase[(size_t)d * 128 + lane * 4];
    const float4 av = *(const float4*)&att1[lane * 4];
    const float4 bb = *(const float4*)&b1[lane * 4];
    const int beg = g_rowptr[d], end = g_rowptr[d + 1];
    const int last = end - 1;

    float m = -INFINITY, s = 0.f;
    float ax = 0.f, ay = 0.f, az = 0.f, aw = 0.f;

    int i4[4];
    float4 r[4];
#pragma unroll
    for (int k = 0; k < 4; k++) {
        int j0 = min(beg + k, last);
        int j4 = min(beg + 4 + k, last);
        int src = g_csr[j0];
        i4[k] = g_csr[j4];
        r[k] = *(const float4*)&xlbase[(size_t)src * 128 + lane * 4];
    }

    for (int j = beg; j < end; j++) {
        int inew = g_csr[min(j + 8, last)];
        float4 rnew = *(const float4*)&xlbase[(size_t)i4[0] * 128 + lane * 4];

        float4 xl = r[0];
        float ex = lrelu(xl.x + xr.x);
        float ey = lrelu(xl.y + xr.y);
        float ez = lrelu(xl.z + xr.z);
        float ew = lrelu(xl.w + xr.w);
        float p = ex * av.x + ey * av.y + ez * av.z + ew * av.w;
        p += __shfl_xor_sync(0xffffffffu, p, 1);
        p += __shfl_xor_sync(0xffffffffu, p, 2);
        float mn = fmaxf(m, p);
        float f  = __expf(m - mn);
        float wt = __expf(p - mn);
        s  = s * f + wt;
        ax = ax * f + xl.x * wt;
        ay = ay * f + xl.y * wt;
        az = az * f + xl.z * wt;
        aw = aw * f + xl.w * wt;
        m = mn;

        r[0] = r[1]; r[1] = r[2]; r[2] = r[3]; r[3] = rnew;
        i4[0] = i4[1]; i4[1] = i4[2]; i4[2] = i4[3]; i4[3] = inew;
    }
    float inv = 1.f / s;
    float4 o;
    o.x = elu1(ax * inv + bb.x);
    o.y = elu1(ay * inv + bb.y);
    o.z = elu1(az * inv + bb.z);
    o.w = elu1(aw * inv + bb.w);
    *(float4*)&g_h1[(size_t)d * 128 + lane * 4] = o;
}

// ---------------- conv2 transforms -----------------------------------------
__global__ void conv2_transform(const float* __restrict__ h,
                                const float* __restrict__ Wl2,
                                const float* __restrict__ Wr2) {
    __shared__ float sw[128 * 32];
    __shared__ float sh[8][128];
    int t = threadIdx.x;
    for (int i = t; i < 128 * 16; i += 256) {
        int k = i >> 4, c = i & 15;
        sw[k * 32 + c]      = Wl2[i];
        sw[k * 32 + 16 + c] = Wr2[i];
    }
    int row0 = blockIdx.x * 8;
    for (int i = t; i < 8 * 128; i += 256) {
        int r = i >> 7;
        sh[r][i & 127] = h[(size_t)(row0 + r) * 128 + (i & 127)];
    }
    __syncthreads();
    int warp = t >> 5, lane = t & 31;
    int row = row0 + warp;
    float acc = 0.f;
#pragma unroll
    for (int k = 0; k < 128; k++) acc += sh[warp][k] * sw[k * 32 + lane];
    g_hlr[(size_t)row * 32 + lane] = acc;
}

// ---------------- conv2 aggregation + log_softmax ---------------------------
__global__ void conv2_agg(const float* __restrict__ att2, const float* __restrict__ b2,
                          float* __restrict__ out) {
    int tid = blockIdx.x * blockDim.x + threadIdx.x;
    int d = tid >> 4;
    int l = tid & 15;
    unsigned hm = 0xFFFFu << (((threadIdx.x & 31) >> 4) * 16);

    float xr = g_hlr[(size_t)d * 32 + 16 + l];
    float a  = att2[l];
    const int beg = g_rowptr[d], end = g_rowptr[d + 1];
    const int last = end - 1;

    float m = -INFINITY, s = 0.f, acc = 0.f;

    int i4[4];
    float r[4];
#pragma unroll
    for (int k = 0; k < 4; k++) {
        int j0 = min(beg + k, last);
        int j4 = min(beg + 4 + k, last);
        int src = g_csr[j0];
        i4[k] = g_csr[j4];
        r[k] = g_hlr[(size_t)src * 32 + l];
    }

    for (int j = beg; j < end; j++) {
        int inew = g_csr[min(j + 8, last)];
        float rnew = g_hlr[(size_t)i4[0] * 32 + l];

        float xl = r[0];
        float p = lrelu(xl + xr) * a;
        p += __shfl_xor_sync(hm, p, 1);
        p += __shfl_xor_sync(hm, p, 2);
        p += __shfl_xor_sync(hm, p, 4);
        p += __shfl_xor_sync(hm, p, 8);
        float mn = fmaxf(m, p);
        float f  = __expf(m - mn);
        float w  = __expf(p - mn);
        s   = s * f + w;
        acc = acc * f + xl * w;
        m = mn;

        r[0] = r[1]; r[1] = r[2]; r[2] = r[3]; r[3] = rnew;
        i4[0] = i4[1]; i4[1] = i4[2]; i4[2] = i4[3]; i4[3] = inew;
    }
    float v = acc / s + b2[l];
    float mm = v;
#pragma unroll
    for (int k = 8; k >= 1; k >>= 1) mm = fmaxf(mm, __shfl_xor_sync(hm, mm, k));
    float pe = expf(v - mm);
    float ss = pe;
#pragma unroll
    for (int k = 8; k >= 1; k >>= 1) ss += __shfl_xor_sync(hm, ss, k);
    out[(size_t)d * 16 + l] = v - mm - logf(ss);
}

// ---------------- side stream (created at static init) ---------------------
static cudaStream_t s_csr = 0;
static cudaEvent_t  ev_fork = 0, ev_join = 0;
namespace {
struct StreamInit {
    StreamInit() {
        cudaStreamCreateWithFlags(&s_csr, cudaStreamNonBlocking);
        cudaEventCreateWithFlags(&ev_fork, cudaEventDisableTiming);
        cudaEventCreateWithFlags(&ev_join, cudaEventDisableTiming);
    }
} s_init;
}

// ---------------- launch ----------------
extern "C" void kernel_launch(void* const* d_in, const int* in_sizes, int n_in,
                              void* d_out, int out_size) {
    const float* x    = (const float*)d_in[0];
    const void*  ei   = d_in[1];
    const float* Wl1  = (const float*)d_in[2];
    const float* Wr1  = (const float*)d_in[3];
    const float* att1 = (const float*)d_in[4];
    const float* b1   = (const float*)d_in[5];
    const float* Wk   = (const float*)d_in[6];
    const float* bk   = (const float*)d_in[7];
    const float* Wl2  = (const float*)d_in[8];
    const float* Wr2  = (const float*)d_in[9];
    const float* att2 = (const float*)d_in[10];
    const float* b2   = (const float*)d_in[11];
    float* out = (float*)d_out;

    cudaFuncSetAttribute(mma_gemm, cudaFuncAttributeMaxDynamicSharedMemorySize, SMEM_MMA_SZ);

    float *xlxr, *h1, *h2;
    cudaGetSymbolAddress((void**)&xlxr, g_xlxr);
    cudaGetSymbolAddress((void**)&h1, g_h1);
    cudaGetSymbolAddress((void**)&h2, g_h2);
    float* xl = xlxr;
    float* xr = xlxr + (size_t)NN * 128;

    // 1: weight fp16 images
    wconv<<<dim3(128, 5), 128>>>(Wl1, Wr1, Wk, Wk + 128 * 128, Wk + 2 * 128 * 128);
    // 2: deg=0 + dtype detect
    init_detect<<<NB, 256>>>(ei);

    // ---- fork: CSR build on side stream, conv1 GEMM on main stream ----
    cudaEventRecord(ev_fork, 0);
    cudaStreamWaitEvent(s_csr, ev_fork, 0);

    // 3: degrees (side stream)
    degree_k <<<(EE + 255) / 256, 256, 0, s_csr>>>(ei);
    // 4: conv1 xl+xr transforms (PROFILED SLOT — tensor cores, overlaps CSR)
    mma_gemm<<<dim3(GX128, 2), 256, SMEM_MMA_SZ>>>(x, 0, 1, xl, xr, nullptr, 0);
    // 5-8: rest of CSR build (side stream)
    scan_part<<<NB, 256, 0, s_csr>>>();
    scan_mid <<<1, 256, 0, s_csr>>>();
    scan_add <<<NB, 256, 0, s_csr>>>();
    scatter_k<<<(EE + 255) / 256, 256, 0, s_csr>>>(ei);
    cudaEventRecord(ev_join, s_csr);

    // ---- join ----
    cudaStreamWaitEvent(0, ev_join, 0);

    // conv1 aggregation (+elu) -> g_h1
    conv1_agg<<<NN / 8, 256>>>(att1, b1);

    // knowledge layers (tensor cores, bias + elu fused)
    mma_gemm<<<dim3(GX128, 1), 256, SMEM_MMA_SZ>>>(h1, 2, 2, h2, h2, bk,       1);
    mma_gemm<<<dim3(GX128, 1), 256, SMEM_MMA_SZ>>>(h2, 3, 3, h1, h1, bk + 128, 1);
    mma_gemm<<<dim3(GX128, 1), 256, SMEM_MMA_SZ>>>(h1, 4, 4, h2, h2, bk + 256, 1);

    // conv2 transforms -> g_hlr
    conv2_transform<<<NN / 8, 256>>>(h2, Wl2, Wr2);

    // conv2 aggregation + log_softmax -> out
    conv2_agg<<<NN / 16, 256>>>(att2, b2, out);
}

// round 14
// speedup vs baseline: 1.5310x; 1.0628x over previous
#include <cuda_runtime.h>
#include <cuda_fp16.h>
#include <math.h>
#include <stdint.h>

#define NN 50000
#define EE 800000
#define ET 850000   // EE + NN self loops
#define NB 196      // ceil(NN/256)
#define GX128 391   // ceil(NN/128)
#define GPAD 136    // padded row: 136 fp16 = 272B (conflict-free ldmatrix)
#define SMEM_MMA_SZ (128 * GPAD * 2)   // 34816 B: single fp16 B image

// ---------------- scratch (static device allocations only) ----------------
__device__ __align__(16) __half g_xl_h[(size_t)NN * 128];
__device__ __align__(16) __half g_xr_h[(size_t)NN * 128];
__device__ __align__(16) __half g_h1h[(size_t)NN * 128];
__device__ __align__(16) __half g_h2h[(size_t)NN * 128];
__device__ float g_hlr[(size_t)NN * 32];
__device__ int   g_deg[NN];
__device__ int   g_rowptr[NN + 1];
__device__ int   g_cursor[NN];
__device__ int   g_csr[ET];
__device__ int   g_part[256];
__device__ int   g_is64;
// weight images: [matrix 0..4] as fp16 [k][n] rows padded to 272B
__device__ __align__(16) __half g_wimg[5][128 * GPAD];

__device__ __forceinline__ float lrelu(float x) { return x > 0.f ? x : 0.2f * x; }
__device__ __forceinline__ float elu1 (float x) { return x > 0.f ? x : expm1f(x); }

__device__ __forceinline__ uint32_t smem_u32(const void* p) {
    uint32_t a;
    asm("{ .reg .u64 t; cvta.to.shared.u64 t, %1; cvt.u32.u64 %0, t; }"
        : "=r"(a) : "l"(p));
    return a;
}
__device__ __forceinline__ uint32_t pkh(float2 f) {
    __half2 h = __float22half2_rn(f);
    return *(uint32_t*)&h;
}

__device__ __forceinline__ void ldsm_x4t(uint32_t& r0, uint32_t& r1,
                                         uint32_t& r2, uint32_t& r3, uint32_t addr) {
    asm volatile("ldmatrix.sync.aligned.m8n8.x4.trans.shared.b16 {%0,%1,%2,%3}, [%4];"
        : "=r"(r0), "=r"(r1), "=r"(r2), "=r"(r3) : "r"(addr));
}
__device__ __forceinline__ void mma16816(float* d, const uint32_t* a,
                                         uint32_t b0, uint32_t b1) {
    asm volatile(
        "mma.sync.aligned.m16n8k16.row.col.f32.f16.f16.f32 "
        "{%0,%1,%2,%3}, {%4,%5,%6,%7}, {%8,%9}, {%0,%1,%2,%3};"
        : "+f"(d[0]), "+f"(d[1]), "+f"(d[2]), "+f"(d[3])
        : "r"(a[0]), "r"(a[1]), "r"(a[2]), "r"(a[3]), "r"(b0), "r"(b1));
}

// ---------------- weight convert kernel: W[k][n] -> fp16 image --------------
__global__ void wconv(const float* __restrict__ w0, const float* __restrict__ w1,
                      const float* __restrict__ w2, const float* __restrict__ w3,
                      const float* __restrict__ w4) {
    int b = blockIdx.y;
    const float* W = (b == 0) ? w0 : (b == 1) ? w1 : (b == 2) ? w2 : (b == 3) ? w3 : w4;
    int k = blockIdx.x, n = threadIdx.x;
    g_wimg[b][k * GPAD + n] = __float2half_rn(W[(size_t)k * 128 + n]);
}

// ---------------- tensor-core GEMM: C[NN,128] = A[NN,128] @ W --------------
// fp16 single-pass, fp32 accum. AHALF: A dtype (0=f32,1=f16). OHALF: C dtype.
// 128(M)x128(N) per 256-thread CTA, two sequential 64-col halves.
template <int AHALF, int OHALF>
__global__ void __launch_bounds__(256) mma_gemm(
    const void* __restrict__ Av, int i0, int i1,
    void* __restrict__ C0v, void* __restrict__ C1v,
    const float* __restrict__ bias, int act) {
    extern __shared__ __align__(16) __half sB[];   // fp16 image [128*GPAD]
    const int t = threadIdx.x, lane = t & 31, wid = t >> 5;
    const int mat = blockIdx.y;
    const int img = mat ? i1 : i0;
    void* Cv = mat ? C1v : C0v;
    const int m0 = blockIdx.x * 128 + wid * 16;

    // stage B image: 34816 B = 2176 uint4
    {
        const uint4* src = (const uint4*)&g_wimg[img][0];
        uint4* dst = (uint4*)sB;
        for (int i = t; i < 2176; i += 256) dst[i] = src[i];
    }
    __syncthreads();

    const int g  = lane >> 2;
    const int cp = (lane & 3) * 2;
    const bool v0 = (m0 + g) < NN;
    const bool v8 = (m0 + g + 8) < NN;

    const int bi   = lane >> 3;
    const int brow = (lane & 7) + (bi & 1) * 8;
    const int bcol = (bi >> 1) * 8;
    const uint32_t sbH = smem_u32(sB);

    const int r0w = m0 + g, r8w = m0 + g + 8;

#pragma unroll
    for (int nh = 0; nh < 2; nh++) {
        const uint32_t hoff = (uint32_t)nh * 128;
        float acc[8][4];
#pragma unroll
        for (int i = 0; i < 8; i++)
#pragma unroll
            for (int j = 0; j < 4; j++) acc[i][j] = 0.f;

        for (int ks = 0; ks < 8; ks++) {
            const int k0 = ks * 16;
            uint32_t ah[4];
            if (AHALF) {
                const __half* Ah = (const __half*)Av;
                ah[0] = v0 ? *(const uint32_t*)&Ah[(size_t)r0w * 128 + k0 + cp]     : 0u;
                ah[1] = v8 ? *(const uint32_t*)&Ah[(size_t)r8w * 128 + k0 + cp]     : 0u;
                ah[2] = v0 ? *(const uint32_t*)&Ah[(size_t)r0w * 128 + k0 + cp + 8] : 0u;
                ah[3] = v8 ? *(const uint32_t*)&Ah[(size_t)r8w * 128 + k0 + cp + 8] : 0u;
            } else {
                const float* Af = (const float*)Av;
                float2 f0 = v0 ? *(const float2*)&Af[(size_t)r0w * 128 + k0 + cp]     : make_float2(0.f, 0.f);
                float2 f1 = v8 ? *(const float2*)&Af[(size_t)r8w * 128 + k0 + cp]     : make_float2(0.f, 0.f);
                float2 f2 = v0 ? *(const float2*)&Af[(size_t)r0w * 128 + k0 + cp + 8] : make_float2(0.f, 0.f);
                float2 f3 = v8 ? *(const float2*)&Af[(size_t)r8w * 128 + k0 + cp + 8] : make_float2(0.f, 0.f);
                ah[0] = pkh(f0); ah[1] = pkh(f1); ah[2] = pkh(f2); ah[3] = pkh(f3);
            }

            const uint32_t rowoff = (uint32_t)((k0 + brow) * GPAD + bcol) * 2 + hoff;
#pragma unroll
            for (int ng = 0; ng < 4; ng++) {
                uint32_t b0, b1, b2, b3;
                ldsm_x4t(b0, b1, b2, b3, sbH + rowoff + ng * 32);
                mma16816(acc[2 * ng],     ah, b0, b1);
                mma16816(acc[2 * ng + 1], ah, b2, b3);
            }
        }

        // epilogue for this 64-col half
#pragma unroll
        for (int nt = 0; nt < 8; nt++) {
            int gc = nh * 64 + nt * 8 + cp;
            float v00 = acc[nt][0], v01 = acc[nt][1];
            float v10 = acc[nt][2], v11 = acc[nt][3];
            if (bias) {
                float b0v = bias[gc], b1v = bias[gc + 1];
                v00 += b0v; v01 += b1v; v10 += b0v; v11 += b1v;
            }
            if (act == 1) { v00 = elu1(v00); v01 = elu1(v01); v10 = elu1(v10); v11 = elu1(v11); }
            if (OHALF) {
                __half* Ch = (__half*)Cv;
                if (v0) *(uint32_t*)&Ch[(size_t)r0w * 128 + gc] = pkh(make_float2(v00, v01));
                if (v8) *(uint32_t*)&Ch[(size_t)r8w * 128 + gc] = pkh(make_float2(v10, v11));
            } else {
                float* Cf = (float*)Cv;
                if (v0) *(float2*)&Cf[(size_t)r0w * 128 + gc] = make_float2(v00, v01);
                if (v8) *(float2*)&Cf[(size_t)r8w * 128 + gc] = make_float2(v10, v11);
            }
        }
    }
}

// ---------------- init deg=0 + dtype detect (block 0) ----------------------
__global__ void init_detect(const void* ei) {
    int i = blockIdx.x * blockDim.x + threadIdx.x;
    if (i < NN) g_deg[i] = 0;
    if (blockIdx.x == 0) {
        __shared__ int cnt;
        if (threadIdx.x == 0) cnt = 0;
        __syncthreads();
        const unsigned* p = (const unsigned*)ei;
        int nz = 0;
        for (int k = threadIdx.x; k < 2048; k += 256)
            if (p[2 * k + 1] != 0u) nz++;
        if (nz) atomicAdd(&cnt, nz);
        __syncthreads();
        if (threadIdx.x == 0) g_is64 = (cnt < 8) ? 1 : 0;
    }
}

__device__ __forceinline__ int edge_val(const void* ei, int idx, int is64) {
    if (is64) return (int)((const long long*)ei)[idx];
    return ((const int*)ei)[idx];
}

__global__ void degree_k(const void* ei) {
    int i = blockIdx.x * blockDim.x + threadIdx.x;
    if (i >= EE) return;
    int is64 = g_is64;
    int dst = edge_val(ei, EE + i, is64);
    atomicAdd(&g_deg[dst], 1);
}

// ---------------- parallel scan over (deg[i]+1) ----------------------------
__global__ void scan_part() {
    int t = threadIdx.x, lane = t & 31, w = t >> 5;
    int i = blockIdx.x * 256 + t;
    int v = (i < NN) ? g_deg[i] + 1 : 0;
#pragma unroll
    for (int off = 16; off >= 1; off >>= 1) v += __shfl_xor_sync(0xffffffffu, v, off);
    __shared__ int ws[8];
    if (lane == 0) ws[w] = v;
    __syncthreads();
    if (t == 0) {
        int s = 0;
#pragma unroll
        for (int k = 0; k < 8; k++) s += ws[k];
        g_part[blockIdx.x] = s;
    }
}

__global__ void scan_mid() {
    int t = threadIdx.x, lane = t & 31, w = t >> 5;
    int d = (t < NB) ? g_part[t] : 0;
    int v = d;
#pragma unroll
    for (int off = 1; off < 32; off <<= 1) {
        int u = __shfl_up_sync(0xffffffffu, v, off);
        if (lane >= off) v += u;
    }
    __shared__ int ws[8];
    if (lane == 31) ws[w] = v;
    __syncthreads();
    if (w == 0 && lane < 8) {
        int s = ws[lane];
#pragma unroll
        for (int off = 1; off < 8; off <<= 1) {
            int u = __shfl_up_sync(0xffu, s, off);
            if (lane >= off) s += u;
        }
        ws[lane] = s;
    }
    __syncthreads();
    int incl = v + (w > 0 ? ws[w - 1] : 0);
    if (t < NB) g_part[t] = incl - d;
    if (t == 255) g_rowptr[NN] = incl;
}

__global__ void scan_add() {
    int t = threadIdx.x, lane = t & 31, w = t >> 5;
    int i = blockIdx.x * 256 + t;
    int d = (i < NN) ? g_deg[i] + 1 : 0;
    int v = d;
#pragma unroll
    for (int off = 1; off < 32; off <<= 1) {
        int u = __shfl_up_sync(0xffffffffu, v, off);
        if (lane >= off) v += u;
    }
    __shared__ int ws[8];
    if (lane == 31) ws[w] = v;
    __syncthreads();
    if (w == 0 && lane < 8) {
        int s = ws[lane];
#pragma unroll
        for (int off = 1; off < 8; off <<= 1) {
            int u = __shfl_up_sync(0xffu, s, off);
            if (lane >= off) s += u;
        }
        ws[lane] = s;
    }
    __syncthreads();
    int excl = g_part[blockIdx.x] + v - d + (w > 0 ? ws[w - 1] : 0);
    if (i < NN) {
        g_rowptr[i] = excl;
        g_csr[excl] = i;
        g_cursor[i] = excl + 1;
    }
}

__global__ void scatter_k(const void* ei) {
    int i = blockIdx.x * blockDim.x + threadIdx.x;
    if (i >= EE) return;
    int is64 = g_is64;
    int s = edge_val(ei, i, is64);
    int d = edge_val(ei, EE + i, is64);
    int pos = atomicAdd(&g_cursor[d], 1);
    g_csr[pos] = s;
}

// ---------------- conv1 aggregation: warp per node, 8-head online softmax --
// fp16 xl/xr gathers (half traffic), fp32 math, fp16 h1 output.
__global__ void conv1_agg(const float* __restrict__ att1, const float* __restrict__ b1) {
    int gw   = (blockIdx.x * blockDim.x + threadIdx.x) >> 5;
    int lane = threadIdx.x & 31;
    int d = gw;
    const int c4 = lane * 4;

    uint2 xru = *(const uint2*)&g_xr_h[(size_t)d * 128 + c4];
    float2 xr01 = __half22float2(*(__half2*)&xru.x);
    float2 xr23 = __half22float2(*(__half2*)&xru.y);
    const float4 av = *(const float4*)&att1[c4];
    const float4 bb = *(const float4*)&b1[c4];
    const int beg = g_rowptr[d], end = g_rowptr[d + 1];
    const int last = end - 1;

    float m = -INFINITY, s = 0.f;
    float ax = 0.f, ay = 0.f, az = 0.f, aw = 0.f;

    int i4[4];
    uint2 r[4];
#pragma unroll
    for (int k = 0; k < 4; k++) {
        int j0 = min(beg + k, last);
        int j4 = min(beg + 4 + k, last);
        int src = g_csr[j0];
        i4[k] = g_csr[j4];
        r[k] = *(const uint2*)&g_xl_h[(size_t)src * 128 + c4];
    }

    for (int j = beg; j < end; j++) {
        int inew = g_csr[min(j + 8, last)];
        uint2 rnew = *(const uint2*)&g_xl_h[(size_t)i4[0] * 128 + c4];

        float2 x01 = __half22float2(*(__half2*)&r[0].x);
        float2 x23 = __half22float2(*(__half2*)&r[0].y);
        float ex = lrelu(x01.x + xr01.x);
        float ey = lrelu(x01.y + xr01.y);
        float ez = lrelu(x23.x + xr23.x);
        float ew = lrelu(x23.y + xr23.y);
        float p = ex * av.x + ey * av.y + ez * av.z + ew * av.w;
        p += __shfl_xor_sync(0xffffffffu, p, 1);
        p += __shfl_xor_sync(0xffffffffu, p, 2);
        float mn = fmaxf(m, p);
        float f  = __expf(m - mn);
        float wt = __expf(p - mn);
        s  = s * f + wt;
        ax = ax * f + x01.x * wt;
        ay = ay * f + x01.y * wt;
        az = az * f + x23.x * wt;
        aw = aw * f + x23.y * wt;
        m = mn;

        r[0] = r[1]; r[1] = r[2]; r[2] = r[3]; r[3] = rnew;
        i4[0] = i4[1]; i4[1] = i4[2]; i4[2] = i4[3]; i4[3] = inew;
    }
    float inv = 1.f / s;
    float o0 = elu1(ax * inv + bb.x);
    float o1 = elu1(ay * inv + bb.y);
    float o2 = elu1(az * inv + bb.z);
    float o3 = elu1(aw * inv + bb.w);
    uint2 ov;
    ov.x = pkh(make_float2(o0, o1));
    ov.y = pkh(make_float2(o2, o3));
    *(uint2*)&g_h1h[(size_t)d * 128 + c4] = ov;
}

// ---------------- conv2 transforms (fp16 h input) ---------------------------
__global__ void conv2_transform(const __half* __restrict__ h,
                                const float* __restrict__ Wl2,
                                const float* __restrict__ Wr2) {
    __shared__ float sw[128 * 32];
    __shared__ float sh[8][128];
    int t = threadIdx.x;
    for (int i = t; i < 128 * 16; i += 256) {
        int k = i >> 4, c = i & 15;
        sw[k * 32 + c]      = Wl2[i];
        sw[k * 32 + 16 + c] = Wr2[i];
    }
    int row0 = blockIdx.x * 8;
    for (int i = t; i < 8 * 128; i += 256) {
        int r = i >> 7;
        sh[r][i & 127] = __half2float(h[(size_t)(row0 + r) * 128 + (i & 127)]);
    }
    __syncthreads();
    int warp = t >> 5, lane = t & 31;
    int row = row0 + warp;
    float acc = 0.f;
#pragma unroll
    for (int k = 0; k < 128; k++) acc += sh[warp][k] * sw[k * 32 + lane];
    g_hlr[(size_t)row * 32 + lane] = acc;
}

// ---------------- conv2 aggregation + log_softmax ---------------------------
__global__ void conv2_agg(const float* __restrict__ att2, const float* __restrict__ b2,
                          float* __restrict__ out) {
    int tid = blockIdx.x * blockDim.x + threadIdx.x;
    int d = tid >> 4;
    int l = tid & 15;
    unsigned hm = 0xFFFFu << (((threadIdx.x & 31) >> 4) * 16);

    float xr = g_hlr[(size_t)d * 32 + 16 + l];
    float a  = att2[l];
    const int beg = g_rowptr[d], end = g_rowptr[d + 1];
    const int last = end - 1;

    float m = -INFINITY, s = 0.f, acc = 0.f;

    int i4[4];
    float r[4];
#pragma unroll
    for (int k = 0; k < 4; k++) {
        int j0 = min(beg + k, last);
        int j4 = min(beg + 4 + k, last);
        int src = g_csr[j0];
        i4[k] = g_csr[j4];
        r[k] = g_hlr[(size_t)src * 32 + l];
    }

    for (int j = beg; j < end; j++) {
        int inew = g_csr[min(j + 8, last)];
        float rnew = g_hlr[(size_t)i4[0] * 32 + l];

        float xl = r[0];
        float p = lrelu(xl + xr) * a;
        p += __shfl_xor_sync(hm, p, 1);
        p += __shfl_xor_sync(hm, p, 2);
        p += __shfl_xor_sync(hm, p, 4);
        p += __shfl_xor_sync(hm, p, 8);
        float mn = fmaxf(m, p);
        float f  = __expf(m - mn);
        float w  = __expf(p - mn);
        s   = s * f + w;
        acc = acc * f + xl * w;
        m = mn;

        r[0] = r[1]; r[1] = r[2]; r[2] = r[3]; r[3] = rnew;
        i4[0] = i4[1]; i4[1] = i4[2]; i4[2] = i4[3]; i4[3] = inew;
    }
    float v = acc / s + b2[l];
    float mm = v;
#pragma unroll
    for (int k = 8; k >= 1; k >>= 1) mm = fmaxf(mm, __shfl_xor_sync(hm, mm, k));
    float pe = expf(v - mm);
    float ss = pe;
#pragma unroll
    for (int k = 8; k >= 1; k >>= 1) ss += __shfl_xor_sync(hm, ss, k);
    out[(size_t)d * 16 + l] = v - mm - logf(ss);
}

// ---------------- side stream (created at static init) ---------------------
static cudaStream_t s_csr = 0;
static cudaEvent_t  ev_fork = 0, ev_join = 0;
namespace {
struct StreamInit {
    StreamInit() {
        cudaStreamCreateWithFlags(&s_csr, cudaStreamNonBlocking);
        cudaEventCreateWithFlags(&ev_fork, cudaEventDisableTiming);
        cudaEventCreateWithFlags(&ev_join, cudaEventDisableTiming);
    }
} s_init;
}

// ---------------- launch ----------------
extern "C" void kernel_launch(void* const* d_in, const int* in_sizes, int n_in,
                              void* d_out, int out_size) {
    const float* x    = (const float*)d_in[0];
    const void*  ei   = d_in[1];
    const float* Wl1  = (const float*)d_in[2];
    const float* Wr1  = (const float*)d_in[3];
    const float* att1 = (const float*)d_in[4];
    const float* b1   = (const float*)d_in[5];
    const float* Wk   = (const float*)d_in[6];
    const float* bk   = (const float*)d_in[7];
    const float* Wl2  = (const float*)d_in[8];
    const float* Wr2  = (const float*)d_in[9];
    const float* att2 = (const float*)d_in[10];
    const float* b2   = (const float*)d_in[11];
    float* out = (float*)d_out;

    cudaFuncSetAttribute(mma_gemm<0, 1>, cudaFuncAttributeMaxDynamicSharedMemorySize, SMEM_MMA_SZ);
    cudaFuncSetAttribute(mma_gemm<1, 1>, cudaFuncAttributeMaxDynamicSharedMemorySize, SMEM_MMA_SZ);

    __half *xlh, *xrh, *h1h, *h2h;
    cudaGetSymbolAddress((void**)&xlh, g_xl_h);
    cudaGetSymbolAddress((void**)&xrh, g_xr_h);
    cudaGetSymbolAddress((void**)&h1h, g_h1h);
    cudaGetSymbolAddress((void**)&h2h, g_h2h);

    // 1: weight fp16 images
    wconv<<<dim3(128, 5), 128>>>(Wl1, Wr1, Wk, Wk + 128 * 128, Wk + 2 * 128 * 128);
    // 2: deg=0 + dtype detect
    init_detect<<<NB, 256>>>(ei);

    // ---- fork: CSR build on side stream, conv1 GEMM on main stream ----
    cudaEventRecord(ev_fork, 0);
    cudaStreamWaitEvent(s_csr, ev_fork, 0);

    // 3: degrees (side stream)
    degree_k <<<(EE + 255) / 256, 256, 0, s_csr>>>(ei);
    // 4: conv1 xl+xr transforms (PROFILED SLOT — fp32 in, fp16 out)
    mma_gemm<0, 1><<<dim3(GX128, 2), 256, SMEM_MMA_SZ>>>(x, 0, 1, xlh, xrh, nullptr, 0);
    // 5-8: rest of CSR build (side stream)
    scan_part<<<NB, 256, 0, s_csr>>>();
    scan_mid <<<1, 256, 0, s_csr>>>();
    scan_add <<<NB, 256, 0, s_csr>>>();
    scatter_k<<<(EE + 255) / 256, 256, 0, s_csr>>>(ei);
    cudaEventRecord(ev_join, s_csr);

    // ---- join ----
    cudaStreamWaitEvent(0, ev_join, 0);

    // conv1 aggregation (+elu) -> h1 (fp16)
    conv1_agg<<<NN / 8, 256>>>(att1, b1);

    // knowledge layers (fp16 in/out, bias + elu fused)
    mma_gemm<1, 1><<<dim3(GX128, 1), 256, SMEM_MMA_SZ>>>(h1h, 2, 2, h2h, h2h, bk,       1);
    mma_gemm<1, 1><<<dim3(GX128, 1), 256, SMEM_MMA_SZ>>>(h2h, 3, 3, h1h, h1h, bk + 128, 1);
    mma_gemm<1, 1><<<dim3(GX128, 1), 256, SMEM_MMA_SZ>>>(h1h, 4, 4, h2h, h2h, bk + 256, 1);

    // conv2 transforms (fp16 h) -> g_hlr (fp32)
    conv2_transform<<<NN / 8, 256>>>(h2h, Wl2, Wr2);

    // conv2 aggregation + log_softmax -> out
    conv2_agg<<<NN / 16, 256>>>(att2, b2, out);
}